// round 2
// baseline (speedup 1.0000x reference)
#include <cuda_runtime.h>
#include <math.h>

// Problem constants
#define Bb    256
#define HWc   196
#define Ec    1024
#define Hc    1024
#define Lc    128
#define Tc    48
#define FCOUT 1154   // L + H + 2

// Scratch (device globals: allocation-free per harness rules)
__device__ float g_img_mean[Bb * Ec];
__device__ float g_h[2][Bb * Hc];       // ping-pong across time steps
__device__ float g_m[Bb * Hc];          // in-place (element owned by one thread)
__device__ float g_base[Bb * 4 * Hc];   // img_mean @ W_ih[:, :E]^T + b_ih + b_hh

__device__ __forceinline__ float sigmoidf_(float x) {
    return 1.0f / (1.0f + expf(-x));
}

// ---------------------------------------------------------------------------
// K1: img_mean = image.mean(axis=1)   [B, E]
// ---------------------------------------------------------------------------
__global__ __launch_bounds__(256) void mean_kernel(const float* __restrict__ img) {
    int idx = blockIdx.x * 256 + threadIdx.x;   // B*E threads
    int b = idx >> 10;
    int e = idx & 1023;
    const float* p = img + (size_t)b * HWc * Ec + e;
    float s = 0.0f;
    #pragma unroll 7
    for (int hw = 0; hw < HWc; ++hw) s += p[(size_t)hw * Ec];
    g_img_mean[idx] = s * (1.0f / HWc);
}

// ---------------------------------------------------------------------------
// K2: setup GEMM  C = act(img_mean @ W^T + bias1 (+bias2))
//     mode 0 -> g_h[0] (tanh), mode 1 -> g_m (tanh), mode 2 -> g_base (none)
//     BM=64, BN=64, BK=32, 256 threads, 4x4 micro-tile
// ---------------------------------------------------------------------------
__global__ __launch_bounds__(256) void setup_gemm(
    const float* __restrict__ W, int ldw,
    const float* __restrict__ bias1,
    const float* __restrict__ bias2,
    int N, int mode)
{
    __shared__ float As[64][36];   // row-major, padded (36*4B, 16B aligned rows)
    __shared__ float Bs[32][64];   // k-major (transposed on store)

    const float* A = g_img_mean;
    float* C = (mode == 0) ? g_h[0] : (mode == 1) ? g_m : g_base;

    int tid = threadIdx.x;
    int bm0 = blockIdx.y * 64, bn0 = blockIdx.x * 64;
    int ty = tid >> 4, tx = tid & 15;
    float acc[4][4] = {};

    int lr = tid >> 2;          // 0..63
    int lk = (tid & 3) * 8;     // 0,8,16,24

    for (int k0 = 0; k0 < Ec; k0 += 32) {
        // A tile (float4, conflict-free)
        const float* ga = A + (size_t)(bm0 + lr) * Ec + k0 + lk;
        float4 a0 = *(const float4*)ga;
        float4 a1 = *(const float4*)(ga + 4);
        *(float4*)&As[lr][lk]     = a0;
        *(float4*)&As[lr][lk + 4] = a1;

        // W tile -> transposed (k-major)
        int wn = bn0 + lr;
        float4 w0 = {0,0,0,0}, w1 = {0,0,0,0};
        if (wn < N) {
            const float* gw = W + (size_t)wn * ldw + k0 + lk;
            w0 = *(const float4*)gw;
            w1 = *(const float4*)(gw + 4);
        }
        Bs[lk + 0][lr] = w0.x; Bs[lk + 1][lr] = w0.y;
        Bs[lk + 2][lr] = w0.z; Bs[lk + 3][lr] = w0.w;
        Bs[lk + 4][lr] = w1.x; Bs[lk + 5][lr] = w1.y;
        Bs[lk + 6][lr] = w1.z; Bs[lk + 7][lr] = w1.w;
        __syncthreads();

        #pragma unroll
        for (int kk = 0; kk < 32; ++kk) {
            float a_[4];
            #pragma unroll
            for (int i = 0; i < 4; ++i) a_[i] = As[ty * 4 + i][kk];
            float4 bv = *(const float4*)&Bs[kk][tx * 4];
            #pragma unroll
            for (int i = 0; i < 4; ++i) {
                acc[i][0] += a_[i] * bv.x;
                acc[i][1] += a_[i] * bv.y;
                acc[i][2] += a_[i] * bv.z;
                acc[i][3] += a_[i] * bv.w;
            }
        }
        __syncthreads();
    }

    #pragma unroll
    for (int i = 0; i < 4; ++i) {
        int r = bm0 + ty * 4 + i;
        #pragma unroll
        for (int j = 0; j < 4; ++j) {
            int n = bn0 + tx * 4 + j;
            if (n < N) {
                float v = acc[i][j] + bias1[n] + (bias2 ? bias2[n] : 0.0f);
                if (mode != 2) v = tanhf(v);
                C[(size_t)r * N + n] = v;
            }
        }
    }
}

// ---------------------------------------------------------------------------
// K3: per-step fused gates GEMM + LSTM pointwise
//     gates[b, g*H + n] = base + label_t@Wih_lab^T + h@Whh^T   (K = 1024 + 128)
//     CTA tile: 64 rows x 32 h-cols x all 4 gates (epilogue has i,f,g,o local)
// ---------------------------------------------------------------------------
__global__ __launch_bounds__(256) void step_gates(
    const float* __restrict__ Whh,     // [4096, 1024]
    const float* __restrict__ Wih,     // [4096, 1152]
    const float* __restrict__ label,   // [256, 48, 128]
    int t)
{
    __shared__ float As[64][36];       // A rows (h then label tail), padded
    __shared__ float Bs[4][32][32];    // per-gate, k-major

    const float* h_in  = g_h[t & 1];
    float*       h_out = g_h[(t + 1) & 1];

    int tid = threadIdx.x;
    int bn0 = blockIdx.x * 32;     // per-gate col tile (32 tiles)
    int bm0 = blockIdx.y * 64;     // row tile (4 tiles)
    int ty = tid >> 4, tx = tid & 15;

    float acc[4][4][2];
    #pragma unroll
    for (int g = 0; g < 4; ++g)
        #pragma unroll
        for (int i = 0; i < 4; ++i) { acc[g][i][0] = 0.f; acc[g][i][1] = 0.f; }

    int lr = tid >> 2, lk = (tid & 3) * 8;           // A loader
    int wrow = tid >> 1, wk = (tid & 1) * 16;        // W loader
    int wg = wrow >> 5, wn = wrow & 31;

    for (int k0 = 0; k0 < 1152; k0 += 32) {
        // A tile: k<1024 -> h_in, k>=1024 -> label[:, t, :]
        const float* ga;
        if (k0 < 1024) ga = h_in + (size_t)(bm0 + lr) * Hc + k0 + lk;
        else           ga = label + ((size_t)(bm0 + lr) * Tc + t) * Lc + (k0 - 1024) + lk;
        float4 a0 = *(const float4*)ga;
        float4 a1 = *(const float4*)(ga + 4);
        *(float4*)&As[lr][lk]     = a0;
        *(float4*)&As[lr][lk + 4] = a1;

        // W tile: gate row gr; k<1024 -> Whh, else -> Wih column k (label slice)
        int gr = wg * Hc + bn0 + wn;
        const float* gwp;
        if (k0 < 1024) gwp = Whh + (size_t)gr * Hc   + k0 + wk;
        else           gwp = Wih + (size_t)gr * 1152 + k0 + wk;
        #pragma unroll
        for (int u = 0; u < 4; ++u) {
            float4 w = *(const float4*)(gwp + u * 4);
            Bs[wg][wk + u*4 + 0][wn] = w.x;
            Bs[wg][wk + u*4 + 1][wn] = w.y;
            Bs[wg][wk + u*4 + 2][wn] = w.z;
            Bs[wg][wk + u*4 + 3][wn] = w.w;
        }
        __syncthreads();

        #pragma unroll
        for (int kk = 0; kk < 32; ++kk) {
            float a_[4];
            #pragma unroll
            for (int i = 0; i < 4; ++i) a_[i] = As[ty * 4 + i][kk];
            #pragma unroll
            for (int g = 0; g < 4; ++g) {
                float2 bv = *(const float2*)&Bs[g][kk][tx * 2];
                #pragma unroll
                for (int i = 0; i < 4; ++i) {
                    acc[g][i][0] += a_[i] * bv.x;
                    acc[g][i][1] += a_[i] * bv.y;
                }
            }
        }
        __syncthreads();
    }

    // Epilogue: LSTM cell update
    #pragma unroll
    for (int i = 0; i < 4; ++i) {
        int r = bm0 + ty * 4 + i;
        const float* baser = g_base + (size_t)r * (4 * Hc);
        #pragma unroll
        for (int j = 0; j < 2; ++j) {
            int n = bn0 + tx * 2 + j;
            float iv = acc[0][i][j] + baser[n];
            float fv = acc[1][i][j] + baser[Hc + n];
            float gv = acc[2][i][j] + baser[2 * Hc + n];
            float ov = acc[3][i][j] + baser[3 * Hc + n];
            size_t idx = (size_t)r * Hc + n;
            float mv = sigmoidf_(fv) * g_m[idx] + sigmoidf_(iv) * tanhf(gv);
            g_m[idx]   = mv;
            h_out[idx] = sigmoidf_(ov) * tanhf(mv);
        }
    }
}

// ---------------------------------------------------------------------------
// K4: per-step fc GEMM + relu/exp/sigmoid/mask epilogue -> 4 output slices
//     BM=32, BN=64, BK=32, 256 threads, 2x4 micro-tile
// ---------------------------------------------------------------------------
__global__ __launch_bounds__(256) void step_fc(
    const float* __restrict__ Wfc,     // [1154, 1024]
    const float* __restrict__ bfc,     // [1154]
    const int*   __restrict__ length,  // [256]
    float* __restrict__ out, int t)
{
    __shared__ float As[32][36];
    __shared__ float Bs[32][64];

    const float* h = g_h[(t + 1) & 1];
    float* lab  = out;
    float* top  = out  + (size_t)Bb * Tc * Lc;
    float* temp = top  + (size_t)Bb * Tc * Hc;
    float* stop = temp + (size_t)Bb * Tc;

    int tid = threadIdx.x;
    int bn0 = blockIdx.x * 64, bm0 = blockIdx.y * 32;
    int ty = tid >> 4, tx = tid & 15;
    float acc[2][4] = {};

    int ar = tid >> 3, ak = (tid & 7) * 4;     // A loader: 1 float4 each
    int wn = tid >> 2, wk = (tid & 3) * 8;     // W loader: 2 float4 each

    for (int k0 = 0; k0 < Hc; k0 += 32) {
        *(float4*)&As[ar][ak] = *(const float4*)(h + (size_t)(bm0 + ar) * Hc + k0 + ak);

        int n = bn0 + wn;
        float4 w0 = {0,0,0,0}, w1 = {0,0,0,0};
        if (n < FCOUT) {
            const float* gw = Wfc + (size_t)n * Hc + k0 + wk;
            w0 = *(const float4*)gw;
            w1 = *(const float4*)(gw + 4);
        }
        Bs[wk + 0][wn] = w0.x; Bs[wk + 1][wn] = w0.y;
        Bs[wk + 2][wn] = w0.z; Bs[wk + 3][wn] = w0.w;
        Bs[wk + 4][wn] = w1.x; Bs[wk + 5][wn] = w1.y;
        Bs[wk + 6][wn] = w1.z; Bs[wk + 7][wn] = w1.w;
        __syncthreads();

        #pragma unroll
        for (int kk = 0; kk < 32; ++kk) {
            float a_[2];
            a_[0] = As[ty * 2 + 0][kk];
            a_[1] = As[ty * 2 + 1][kk];
            float4 bv = *(const float4*)&Bs[kk][tx * 4];
            #pragma unroll
            for (int i = 0; i < 2; ++i) {
                acc[i][0] += a_[i] * bv.x;
                acc[i][1] += a_[i] * bv.y;
                acc[i][2] += a_[i] * bv.z;
                acc[i][3] += a_[i] * bv.w;
            }
        }
        __syncthreads();
    }

    #pragma unroll
    for (int i = 0; i < 2; ++i) {
        int r = bm0 + ty * 2 + i;
        float mask = (t < length[r]) ? 1.0f : 0.0f;
        size_t bt = (size_t)r * Tc + t;
        #pragma unroll
        for (int j = 0; j < 4; ++j) {
            int n = bn0 + tx * 4 + j;
            if (n < FCOUT) {
                float v = fmaxf(acc[i][j] + bfc[n], 0.0f);   // relu
                if (n < Lc)               lab[bt * Lc + n]        = v * mask;
                else if (n < Lc + Hc)     top[bt * Hc + (n - Lc)] = v * mask;
                else if (n == Lc + Hc)    temp[bt]                = expf(v) * mask;
                else                      stop[bt]                = sigmoidf_(v) * mask;
            }
        }
    }
}

// ---------------------------------------------------------------------------
// Launch: mean -> h0/m0/base setup -> 48 x (gates+LSTM, fc+outputs)
// ---------------------------------------------------------------------------
extern "C" void kernel_launch(void* const* d_in, const int* in_sizes, int n_in,
                              void* d_out, int out_size)
{
    const float* image  = (const float*)d_in[0];
    const float* label  = (const float*)d_in[1];
    const int*   length = (const int*)  d_in[2];
    const float* W_h    = (const float*)d_in[3];
    const float* b_h    = (const float*)d_in[4];
    const float* W_m    = (const float*)d_in[5];
    const float* b_m    = (const float*)d_in[6];
    const float* W_ih   = (const float*)d_in[7];
    const float* W_hh   = (const float*)d_in[8];
    const float* b_ih   = (const float*)d_in[9];
    const float* b_hh   = (const float*)d_in[10];
    const float* W_fc   = (const float*)d_in[11];
    const float* b_fc   = (const float*)d_in[12];
    float* out = (float*)d_out;

    mean_kernel<<<(Bb * Ec) / 256, 256>>>(image);

    // h0 = tanh(img_mean @ W_h^T + b_h), m0 likewise,
    // base = img_mean @ W_ih[:, :E]^T + b_ih + b_hh  (hoisted time-invariant)
    setup_gemm<<<dim3(16, 4), 256>>>(W_h,  Ec,   b_h,  nullptr, Hc,     0);
    setup_gemm<<<dim3(16, 4), 256>>>(W_m,  Ec,   b_m,  nullptr, Hc,     1);
    setup_gemm<<<dim3(64, 4), 256>>>(W_ih, 1152, b_ih, b_hh,    4 * Hc, 2);

    for (int t = 0; t < Tc; ++t) {
        step_gates<<<dim3(32, 4), 256>>>(W_hh, W_ih, label, t);
        step_fc<<<dim3(19, 8), 256>>>(W_fc, b_fc, length, out, t);
    }
}

// round 4
// speedup vs baseline: 1.0014x; 1.0014x over previous
#include <cuda_runtime.h>
#include <math.h>

// Problem constants
#define Bb    256
#define HWc   196
#define Ec    1024
#define Hc    1024
#define Lc    128
#define Tc    48
#define FCOUT 1154   // L + H + 2

// Scratch (device globals: allocation-free per harness rules)
__device__ float g_img_mean[Bb * Ec];
__device__ float g_h[2][Bb * Hc];       // ping-pong across time steps
__device__ float g_m[Bb * Hc];          // in-place (element owned by one thread)
__device__ float g_base[Bb * 4 * Hc];   // img_mean @ W_ih[:, :E]^T + b_ih + b_hh

__device__ __forceinline__ float sigmoidf_(float x) {
    return 1.0f / (1.0f + expf(-x));
}

// ---------------------------------------------------------------------------
// K1: img_mean = image.mean(axis=1)   [B, E]
// ---------------------------------------------------------------------------
__global__ __launch_bounds__(256) void mean_kernel(const float* __restrict__ img) {
    int idx = blockIdx.x * 256 + threadIdx.x;   // B*E threads
    int b = idx >> 10;
    int e = idx & 1023;
    const float* p = img + (size_t)b * HWc * Ec + e;
    float s = 0.0f;
    #pragma unroll 7
    for (int hw = 0; hw < HWc; ++hw) s += p[(size_t)hw * Ec];
    g_img_mean[idx] = s * (1.0f / HWc);
}

// ---------------------------------------------------------------------------
// K2: setup GEMM  C = act(img_mean @ W^T + bias1 (+bias2))
//     mode 0 -> g_h[0] (tanh), mode 1 -> g_m (tanh), mode 2 -> g_base (none)
//     BM=64, BN=64, BK=32, 256 threads, 4x4 micro-tile
// ---------------------------------------------------------------------------
__global__ __launch_bounds__(256) void setup_gemm(
    const float* __restrict__ W, int ldw,
    const float* __restrict__ bias1,
    const float* __restrict__ bias2,
    int N, int mode)
{
    __shared__ float As[64][36];   // row-major, padded (36*4B, 16B aligned rows)
    __shared__ float Bs[32][64];   // k-major (transposed on store)

    const float* A = g_img_mean;
    float* C = (mode == 0) ? g_h[0] : (mode == 1) ? g_m : g_base;

    int tid = threadIdx.x;
    int bm0 = blockIdx.y * 64, bn0 = blockIdx.x * 64;
    int ty = tid >> 4, tx = tid & 15;
    float acc[4][4] = {};

    int lr = tid >> 2;          // 0..63
    int lk = (tid & 3) * 8;     // 0,8,16,24

    for (int k0 = 0; k0 < Ec; k0 += 32) {
        // A tile (float4, conflict-free)
        const float* ga = A + (size_t)(bm0 + lr) * Ec + k0 + lk;
        float4 a0 = *(const float4*)ga;
        float4 a1 = *(const float4*)(ga + 4);
        *(float4*)&As[lr][lk]     = a0;
        *(float4*)&As[lr][lk + 4] = a1;

        // W tile -> transposed (k-major)
        int wn = bn0 + lr;
        float4 w0 = {0,0,0,0}, w1 = {0,0,0,0};
        if (wn < N) {
            const float* gw = W + (size_t)wn * ldw + k0 + lk;
            w0 = *(const float4*)gw;
            w1 = *(const float4*)(gw + 4);
        }
        Bs[lk + 0][lr] = w0.x; Bs[lk + 1][lr] = w0.y;
        Bs[lk + 2][lr] = w0.z; Bs[lk + 3][lr] = w0.w;
        Bs[lk + 4][lr] = w1.x; Bs[lk + 5][lr] = w1.y;
        Bs[lk + 6][lr] = w1.z; Bs[lk + 7][lr] = w1.w;
        __syncthreads();

        #pragma unroll
        for (int kk = 0; kk < 32; ++kk) {
            float a_[4];
            #pragma unroll
            for (int i = 0; i < 4; ++i) a_[i] = As[ty * 4 + i][kk];
            float4 bv = *(const float4*)&Bs[kk][tx * 4];
            #pragma unroll
            for (int i = 0; i < 4; ++i) {
                acc[i][0] += a_[i] * bv.x;
                acc[i][1] += a_[i] * bv.y;
                acc[i][2] += a_[i] * bv.z;
                acc[i][3] += a_[i] * bv.w;
            }
        }
        __syncthreads();
    }

    #pragma unroll
    for (int i = 0; i < 4; ++i) {
        int r = bm0 + ty * 4 + i;
        #pragma unroll
        for (int j = 0; j < 4; ++j) {
            int n = bn0 + tx * 4 + j;
            if (n < N) {
                float v = acc[i][j] + bias1[n] + (bias2 ? bias2[n] : 0.0f);
                if (mode != 2) v = tanhf(v);
                C[(size_t)r * N + n] = v;
            }
        }
    }
}

// ---------------------------------------------------------------------------
// K3: per-step fused gates GEMM + LSTM pointwise
//     gates[b, g*H + n] = base + label_t@Wih_lab^T + h@Whh^T   (K = 1024 + 128)
//     CTA tile: 64 rows x 32 h-cols x all 4 gates (epilogue has i,f,g,o local)
// ---------------------------------------------------------------------------
__global__ __launch_bounds__(256) void step_gates(
    const float* __restrict__ Whh,     // [4096, 1024]
    const float* __restrict__ Wih,     // [4096, 1152]
    const float* __restrict__ label,   // [256, 48, 128]
    int t)
{
    __shared__ float As[64][36];       // A rows (h then label tail), padded
    __shared__ float Bs[4][32][32];    // per-gate, k-major

    const float* h_in  = g_h[t & 1];
    float*       h_out = g_h[(t + 1) & 1];

    int tid = threadIdx.x;
    int bn0 = blockIdx.x * 32;     // per-gate col tile (32 tiles)
    int bm0 = blockIdx.y * 64;     // row tile (4 tiles)
    int ty = tid >> 4, tx = tid & 15;

    float acc[4][4][2];
    #pragma unroll
    for (int g = 0; g < 4; ++g)
        #pragma unroll
        for (int i = 0; i < 4; ++i) { acc[g][i][0] = 0.f; acc[g][i][1] = 0.f; }

    int lr = tid >> 2, lk = (tid & 3) * 8;           // A loader
    int wrow = tid >> 1, wk = (tid & 1) * 16;        // W loader
    int wg = wrow >> 5, wn = wrow & 31;

    for (int k0 = 0; k0 < 1152; k0 += 32) {
        // A tile: k<1024 -> h_in, k>=1024 -> label[:, t, :]
        const float* ga;
        if (k0 < 1024) ga = h_in + (size_t)(bm0 + lr) * Hc + k0 + lk;
        else           ga = label + ((size_t)(bm0 + lr) * Tc + t) * Lc + (k0 - 1024) + lk;
        float4 a0 = *(const float4*)ga;
        float4 a1 = *(const float4*)(ga + 4);
        *(float4*)&As[lr][lk]     = a0;
        *(float4*)&As[lr][lk + 4] = a1;

        // W tile: gate row gr; k<1024 -> Whh, else -> Wih column k (label slice)
        int gr = wg * Hc + bn0 + wn;
        const float* gwp;
        if (k0 < 1024) gwp = Whh + (size_t)gr * Hc   + k0 + wk;
        else           gwp = Wih + (size_t)gr * 1152 + k0 + wk;
        #pragma unroll
        for (int u = 0; u < 4; ++u) {
            float4 w = *(const float4*)(gwp + u * 4);
            Bs[wg][wk + u*4 + 0][wn] = w.x;
            Bs[wg][wk + u*4 + 1][wn] = w.y;
            Bs[wg][wk + u*4 + 2][wn] = w.z;
            Bs[wg][wk + u*4 + 3][wn] = w.w;
        }
        __syncthreads();

        #pragma unroll
        for (int kk = 0; kk < 32; ++kk) {
            float a_[4];
            #pragma unroll
            for (int i = 0; i < 4; ++i) a_[i] = As[ty * 4 + i][kk];
            #pragma unroll
            for (int g = 0; g < 4; ++g) {
                float2 bv = *(const float2*)&Bs[g][kk][tx * 2];
                #pragma unroll
                for (int i = 0; i < 4; ++i) {
                    acc[g][i][0] += a_[i] * bv.x;
                    acc[g][i][1] += a_[i] * bv.y;
                }
            }
        }
        __syncthreads();
    }

    // Epilogue: LSTM cell update
    #pragma unroll
    for (int i = 0; i < 4; ++i) {
        int r = bm0 + ty * 4 + i;
        const float* baser = g_base + (size_t)r * (4 * Hc);
        #pragma unroll
        for (int j = 0; j < 2; ++j) {
            int n = bn0 + tx * 2 + j;
            float iv = acc[0][i][j] + baser[n];
            float fv = acc[1][i][j] + baser[Hc + n];
            float gv = acc[2][i][j] + baser[2 * Hc + n];
            float ov = acc[3][i][j] + baser[3 * Hc + n];
            size_t idx = (size_t)r * Hc + n;
            float mv = sigmoidf_(fv) * g_m[idx] + sigmoidf_(iv) * tanhf(gv);
            g_m[idx]   = mv;
            h_out[idx] = sigmoidf_(ov) * tanhf(mv);
        }
    }
}

// ---------------------------------------------------------------------------
// K4: per-step fc GEMM + relu/exp/sigmoid/mask epilogue -> 4 output slices
//     BM=32, BN=64, BK=32, 256 threads, 2x4 micro-tile
// ---------------------------------------------------------------------------
__global__ __launch_bounds__(256) void step_fc(
    const float* __restrict__ Wfc,     // [1154, 1024]
    const float* __restrict__ bfc,     // [1154]
    const int*   __restrict__ length,  // [256]
    float* __restrict__ out, int t)
{
    __shared__ float As[32][36];
    __shared__ float Bs[32][64];

    const float* h = g_h[(t + 1) & 1];
    float* lab  = out;
    float* top  = out  + (size_t)Bb * Tc * Lc;
    float* temp = top  + (size_t)Bb * Tc * Hc;
    float* stop = temp + (size_t)Bb * Tc;

    int tid = threadIdx.x;
    int bn0 = blockIdx.x * 64, bm0 = blockIdx.y * 32;
    int ty = tid >> 4, tx = tid & 15;
    float acc[2][4] = {};

    int ar = tid >> 3, ak = (tid & 7) * 4;     // A loader: 1 float4 each
    int wn = tid >> 2, wk = (tid & 3) * 8;     // W loader: 2 float4 each

    for (int k0 = 0; k0 < Hc; k0 += 32) {
        *(float4*)&As[ar][ak] = *(const float4*)(h + (size_t)(bm0 + ar) * Hc + k0 + ak);

        int n = bn0 + wn;
        float4 w0 = {0,0,0,0}, w1 = {0,0,0,0};
        if (n < FCOUT) {
            const float* gw = Wfc + (size_t)n * Hc + k0 + wk;
            w0 = *(const float4*)gw;
            w1 = *(const float4*)(gw + 4);
        }
        Bs[wk + 0][wn] = w0.x; Bs[wk + 1][wn] = w0.y;
        Bs[wk + 2][wn] = w0.z; Bs[wk + 3][wn] = w0.w;
        Bs[wk + 4][wn] = w1.x; Bs[wk + 5][wn] = w1.y;
        Bs[wk + 6][wn] = w1.z; Bs[wk + 7][wn] = w1.w;
        __syncthreads();

        #pragma unroll
        for (int kk = 0; kk < 32; ++kk) {
            float a_[2];
            a_[0] = As[ty * 2 + 0][kk];
            a_[1] = As[ty * 2 + 1][kk];
            float4 bv = *(const float4*)&Bs[kk][tx * 4];
            #pragma unroll
            for (int i = 0; i < 2; ++i) {
                acc[i][0] += a_[i] * bv.x;
                acc[i][1] += a_[i] * bv.y;
                acc[i][2] += a_[i] * bv.z;
                acc[i][3] += a_[i] * bv.w;
            }
        }
        __syncthreads();
    }

    #pragma unroll
    for (int i = 0; i < 2; ++i) {
        int r = bm0 + ty * 2 + i;
        float mask = (t < length[r]) ? 1.0f : 0.0f;
        size_t bt = (size_t)r * Tc + t;
        #pragma unroll
        for (int j = 0; j < 4; ++j) {
            int n = bn0 + tx * 4 + j;
            if (n < FCOUT) {
                float v = fmaxf(acc[i][j] + bfc[n], 0.0f);   // relu
                if (n < Lc)               lab[bt * Lc + n]        = v * mask;
                else if (n < Lc + Hc)     top[bt * Hc + (n - Lc)] = v * mask;
                else if (n == Lc + Hc)    temp[bt]                = expf(v) * mask;
                else                      stop[bt]                = sigmoidf_(v) * mask;
            }
        }
    }
}

// ---------------------------------------------------------------------------
// Launch: mean -> h0/m0/base setup -> 48 x (gates+LSTM, fc+outputs)
// ---------------------------------------------------------------------------
extern "C" void kernel_launch(void* const* d_in, const int* in_sizes, int n_in,
                              void* d_out, int out_size)
{
    const float* image  = (const float*)d_in[0];
    const float* label  = (const float*)d_in[1];
    const int*   length = (const int*)  d_in[2];
    const float* W_h    = (const float*)d_in[3];
    const float* b_h    = (const float*)d_in[4];
    const float* W_m    = (const float*)d_in[5];
    const float* b_m    = (const float*)d_in[6];
    const float* W_ih   = (const float*)d_in[7];
    const float* W_hh   = (const float*)d_in[8];
    const float* b_ih   = (const float*)d_in[9];
    const float* b_hh   = (const float*)d_in[10];
    const float* W_fc   = (const float*)d_in[11];
    const float* b_fc   = (const float*)d_in[12];
    float* out = (float*)d_out;

    mean_kernel<<<(Bb * Ec) / 256, 256>>>(image);

    // h0 = tanh(img_mean @ W_h^T + b_h), m0 likewise,
    // base = img_mean @ W_ih[:, :E]^T + b_ih + b_hh  (hoisted time-invariant)
    setup_gemm<<<dim3(16, 4), 256>>>(W_h,  Ec,   b_h,  nullptr, Hc,     0);
    setup_gemm<<<dim3(16, 4), 256>>>(W_m,  Ec,   b_m,  nullptr, Hc,     1);
    setup_gemm<<<dim3(64, 4), 256>>>(W_ih, 1152, b_ih, b_hh,    4 * Hc, 2);

    for (int t = 0; t < Tc; ++t) {
        step_gates<<<dim3(32, 4), 256>>>(W_hh, W_ih, label, t);
        step_fc<<<dim3(19, 8), 256>>>(W_fc, b_fc, length, out, t);
    }
}

// round 6
// speedup vs baseline: 1.8470x; 1.8444x over previous
#include <cuda_runtime.h>
#include <cuda_bf16.h>
#include <math.h>
#include <stdint.h>

#define Bb    256
#define HWc   196
#define Ec    1024
#define Hc    1024
#define Lc    128
#define Tc    48
#define FCOUT 1154
#define FCPAD 1280   // 10 * 128

// ---------------- device-global scratch (allocation-free) ----------------
__device__ float g_m[Bb * Hc];
__device__ float g_base[Bb * 4 * Hc];
__device__ float g_gates[Bb * 4 * Hc];
__device__ __nv_bfloat16 g_h_hi[Bb * Hc],  g_h_lo[Bb * Hc];
__device__ __nv_bfloat16 g_im_hi[Bb * Ec], g_im_lo[Bb * Ec];
__device__ __nv_bfloat16 g_Whh_hi[4096 * 1024], g_Whh_lo[4096 * 1024];
__device__ __nv_bfloat16 g_Wih_hi[4096 * 1024], g_Wih_lo[4096 * 1024];
__device__ __nv_bfloat16 g_Wlab_hi[4096 * 128], g_Wlab_lo[4096 * 128];
__device__ __nv_bfloat16 g_Wh_hi[1024 * 1024],  g_Wh_lo[1024 * 1024];
__device__ __nv_bfloat16 g_Wm_hi[1024 * 1024],  g_Wm_lo[1024 * 1024];
__device__ __nv_bfloat16 g_Wfc_hi[FCPAD * 1024], g_Wfc_lo[FCPAD * 1024];
__device__ __nv_bfloat16 g_lab_hi[Bb * Tc * Lc], g_lab_lo[Bb * Tc * Lc];

// ---------------- helpers ----------------
__device__ __forceinline__ float sigmoidf_(float x) { return 1.0f / (1.0f + expf(-x)); }

__device__ __forceinline__ void bf16split(float v, __nv_bfloat16& h, __nv_bfloat16& l) {
    h = __float2bfloat16(v);
    l = __float2bfloat16(v - __bfloat162float(h));
}
__device__ __forceinline__ uint32_t smem_u32(const void* p) {
    return (uint32_t)__cvta_generic_to_shared(p);
}
__device__ __forceinline__ void cpasync16(uint32_t s, const void* g) {
    asm volatile("cp.async.cg.shared.global [%0], [%1], 16;\n" :: "r"(s), "l"(g) : "memory");
}
#define CP_COMMIT() asm volatile("cp.async.commit_group;\n" ::: "memory")
#define CP_WAIT2()  asm volatile("cp.async.wait_group 2;\n" ::: "memory")

__device__ __forceinline__ void ldsm4(uint32_t* r, uint32_t a) {
    asm volatile("ldmatrix.sync.aligned.m8n8.x4.shared.b16 {%0,%1,%2,%3}, [%4];"
        : "=r"(r[0]), "=r"(r[1]), "=r"(r[2]), "=r"(r[3]) : "r"(a));
}
__device__ __forceinline__ void ldsm2(uint32_t* r, uint32_t a) {
    asm volatile("ldmatrix.sync.aligned.m8n8.x2.shared.b16 {%0,%1}, [%2];"
        : "=r"(r[0]), "=r"(r[1]) : "r"(a));
}
__device__ __forceinline__ void mma_bf16(float* c, const uint32_t* a, const uint32_t* b) {
    asm volatile("mma.sync.aligned.m16n8k16.row.col.f32.bf16.bf16.f32 "
        "{%0,%1,%2,%3}, {%4,%5,%6,%7}, {%8,%9}, {%0,%1,%2,%3};"
        : "+f"(c[0]), "+f"(c[1]), "+f"(c[2]), "+f"(c[3])
        : "r"(a[0]), "r"(a[1]), "r"(a[2]), "r"(a[3]), "r"(b[0]), "r"(b[1]));
}

// ---------------- K1: mean + split ----------------
__global__ __launch_bounds__(256) void mean_split(const float* __restrict__ img) {
    int idx = blockIdx.x * 256 + threadIdx.x;   // B*E
    int b = idx >> 10, e = idx & 1023;
    const float* p = img + (size_t)b * HWc * Ec + e;
    float s = 0.0f;
    #pragma unroll 7
    for (int hw = 0; hw < HWc; ++hw) s += p[(size_t)hw * Ec];
    __nv_bfloat16 h, l;
    bf16split(s * (1.0f / HWc), h, l);
    g_im_hi[idx] = h; g_im_lo[idx] = l;
}

// ---------------- K2: fp32 -> bf16 hi/lo split (padded rows zeroed) ------
__global__ __launch_bounds__(256) void split_kernel(
    const float* __restrict__ in, int ld, int c0, int cols,
    int rows_valid, int total, int which)
{
    int idx = blockIdx.x * 256 + threadIdx.x;
    if (idx >= total) return;
    int r = idx / cols, c = idx % cols;
    float v = (r < rows_valid) ? in[(size_t)r * ld + c0 + c] : 0.0f;
    __nv_bfloat16 h, l;
    bf16split(v, h, l);
    __nv_bfloat16 *ph, *pl;
    switch (which) {
        case 0: ph = g_Wh_hi;  pl = g_Wh_lo;  break;
        case 1: ph = g_Wm_hi;  pl = g_Wm_lo;  break;
        case 2: ph = g_Wih_hi; pl = g_Wih_lo; break;
        case 3: ph = g_Wlab_hi;pl = g_Wlab_lo;break;
        case 4: ph = g_Whh_hi; pl = g_Whh_lo; break;
        case 5: ph = g_Wfc_hi; pl = g_Wfc_lo; break;
        default:ph = g_lab_hi; pl = g_lab_lo; break;
    }
    ph[idx] = h; pl[idx] = l;
}

// ---------------- K3: bf16x2 3-term tensor-core GEMM ---------------------
// CTA tile 64x128, 128 threads (4 warps, warp m64xn32), 4-stage cp.async.
// MODE 0: gates  A=h(+label tail, K=1152) B=Whh/Wlab  -> g_gates (raw fp32)
// MODE 1: base   A=im B=Wih  (+b_ih+b_hh)             -> g_base
// MODE 2: h0     A=im B=Wh   tanh                     -> g_h hi/lo
// MODE 3: m0     A=im B=Wm   tanh                     -> g_m
// MODE 4: fc     A=h  B=Wfc  relu/exp/sigmoid/mask    -> out slices
// smem per stage: Ahi 5120 | Alo 5120 | Bhi 10240 | Blo 10240 (stride 80B)
template<int MODE>
__global__ void __launch_bounds__(128) mma_big(
    const float* __restrict__ bias1, const float* __restrict__ bias2,
    const int* __restrict__ length, float* __restrict__ out, int t)
{
    constexpr int K   = (MODE == 0) ? 1152 : 1024;
    constexpr int NIT = K / 32;
    extern __shared__ char smem[];
    const uint32_t smb = smem_u32(smem);

    const int tid = threadIdx.x, lane = tid & 31, w = tid >> 5;
    const int bm0 = blockIdx.y * 64, bn0 = blockIdx.x * 128;

    float acc[4][4][4];
    #pragma unroll
    for (int a = 0; a < 4; ++a)
        #pragma unroll
        for (int b = 0; b < 4; ++b)
            #pragma unroll
            for (int c = 0; c < 4; ++c) acc[a][b][c] = 0.0f;

    auto load_stage = [&](int st, int k0) {
        uint32_t sb = smb + (uint32_t)st * 30720u;
        #pragma unroll
        for (int s = 0; s < 2; ++s) {                 // A: 64 rows x 4 chunks
            int slot = tid + s * 128;
            int r = slot >> 2, ch = slot & 3, k = k0 + ch * 8;
            const __nv_bfloat16 *gh, *gl;
            if (MODE == 0 && k >= 1024) {
                size_t off = ((size_t)(bm0 + r) * Tc + t) * Lc + (k - 1024);
                gh = g_lab_hi + off; gl = g_lab_lo + off;
            } else {
                size_t off = (size_t)(bm0 + r) * 1024 + k;
                if (MODE == 0 || MODE == 4) { gh = g_h_hi + off;  gl = g_h_lo + off; }
                else                         { gh = g_im_hi + off; gl = g_im_lo + off; }
            }
            uint32_t so = (uint32_t)(r * 80 + ch * 16);
            cpasync16(sb + so, gh);
            cpasync16(sb + 5120u + so, gl);
        }
        #pragma unroll
        for (int s = 0; s < 4; ++s) {                 // B: 128 rows x 4 chunks
            int slot = tid + s * 128;
            int r = slot >> 2, ch = slot & 3, k = k0 + ch * 8;
            int gr = bn0 + r;
            const __nv_bfloat16 *gh, *gl;
            if (MODE == 0 && k >= 1024) {
                size_t off = (size_t)gr * 128 + (k - 1024);
                gh = g_Wlab_hi + off; gl = g_Wlab_lo + off;
            } else {
                size_t off = (size_t)gr * 1024 + k;
                if      (MODE == 0) { gh = g_Whh_hi + off; gl = g_Whh_lo + off; }
                else if (MODE == 1) { gh = g_Wih_hi + off; gl = g_Wih_lo + off; }
                else if (MODE == 2) { gh = g_Wh_hi + off;  gl = g_Wh_lo + off; }
                else if (MODE == 3) { gh = g_Wm_hi + off;  gl = g_Wm_lo + off; }
                else                { gh = g_Wfc_hi + off; gl = g_Wfc_lo + off; }
            }
            uint32_t so = (uint32_t)(r * 80 + ch * 16);
            cpasync16(sb + 10240u + so, gh);
            cpasync16(sb + 20480u + so, gl);
        }
    };

    load_stage(0, 0);  CP_COMMIT();
    load_stage(1, 32); CP_COMMIT();

    const uint32_t aOff = (uint32_t)((lane & 15) * 80 + (lane >> 4) * 16);
    const uint32_t bOff = (uint32_t)((w * 32 + (lane & 7)) * 80 + ((lane >> 3) & 1) * 16);

    for (int it = 0; it < NIT; ++it) {
        if (it + 2 < NIT) load_stage((it + 2) & 3, (it + 2) * 32);
        CP_COMMIT();
        CP_WAIT2();
        __syncthreads();
        uint32_t sb = smb + (uint32_t)(it & 3) * 30720u;
        #pragma unroll
        for (int kh = 0; kh < 2; ++kh) {
            uint32_t afh[4][4], afl[4][4];
            #pragma unroll
            for (int mi = 0; mi < 4; ++mi) {
                uint32_t ad = sb + aOff + (uint32_t)(mi * 1280 + kh * 32);
                ldsm4(afh[mi], ad);
                ldsm4(afl[mi], ad + 5120u);
            }
            #pragma unroll
            for (int ni = 0; ni < 4; ++ni) {
                uint32_t bd = sb + 10240u + bOff + (uint32_t)(ni * 640 + kh * 32);
                uint32_t bfh[2], bfl[2];
                ldsm2(bfh, bd);
                ldsm2(bfl, bd + 10240u);
                #pragma unroll
                for (int mi = 0; mi < 4; ++mi) {
                    mma_bf16(acc[mi][ni], afh[mi], bfh);
                    mma_bf16(acc[mi][ni], afl[mi], bfh);
                    mma_bf16(acc[mi][ni], afh[mi], bfl);
                }
            }
        }
        __syncthreads();
    }

    // ---------------- epilogue ----------------
    #pragma unroll
    for (int mi = 0; mi < 4; ++mi) {
        int r0 = bm0 + mi * 16 + (lane >> 2);
        #pragma unroll
        for (int ni = 0; ni < 4; ++ni) {
            int c0 = bn0 + w * 32 + ni * 8 + (lane & 3) * 2;
            float* a = acc[mi][ni];
            if (MODE == 0) {
                *(float2*)&g_gates[(size_t)r0 * 4096 + c0]       = make_float2(a[0], a[1]);
                *(float2*)&g_gates[(size_t)(r0 + 8) * 4096 + c0] = make_float2(a[2], a[3]);
            } else if (MODE == 1) {
                float b0 = bias1[c0] + bias2[c0], b1 = bias1[c0 + 1] + bias2[c0 + 1];
                *(float2*)&g_base[(size_t)r0 * 4096 + c0]       = make_float2(a[0] + b0, a[1] + b1);
                *(float2*)&g_base[(size_t)(r0 + 8) * 4096 + c0] = make_float2(a[2] + b0, a[3] + b1);
            } else if (MODE == 2 || MODE == 3) {
                float b0 = bias1[c0], b1 = bias1[c0 + 1];
                float v0 = tanhf(a[0] + b0), v1 = tanhf(a[1] + b1);
                float v2 = tanhf(a[2] + b0), v3 = tanhf(a[3] + b1);
                if (MODE == 2) {
                    __nv_bfloat16 h0, l0, h1, l1;
                    __nv_bfloat162 hh, ll;
                    bf16split(v0, h0, l0); bf16split(v1, h1, l1);
                    hh.x = h0; hh.y = h1; ll.x = l0; ll.y = l1;
                    *(__nv_bfloat162*)&g_h_hi[(size_t)r0 * 1024 + c0] = hh;
                    *(__nv_bfloat162*)&g_h_lo[(size_t)r0 * 1024 + c0] = ll;
                    bf16split(v2, h0, l0); bf16split(v3, h1, l1);
                    hh.x = h0; hh.y = h1; ll.x = l0; ll.y = l1;
                    *(__nv_bfloat162*)&g_h_hi[(size_t)(r0 + 8) * 1024 + c0] = hh;
                    *(__nv_bfloat162*)&g_h_lo[(size_t)(r0 + 8) * 1024 + c0] = ll;
                } else {
                    g_m[(size_t)r0 * 1024 + c0]           = v0;
                    g_m[(size_t)r0 * 1024 + c0 + 1]       = v1;
                    g_m[(size_t)(r0 + 8) * 1024 + c0]     = v2;
                    g_m[(size_t)(r0 + 8) * 1024 + c0 + 1] = v3;
                }
            } else {   // MODE 4: fc outputs
                float* lab  = out;
                float* top  = out  + (size_t)Bb * Tc * Lc;
                float* temp = top  + (size_t)Bb * Tc * Hc;
                float* stop = temp + (size_t)Bb * Tc;
                #pragma unroll
                for (int half = 0; half < 2; ++half) {
                    int r = r0 + half * 8;
                    float mask = (t < length[r]) ? 1.0f : 0.0f;
                    size_t bt = (size_t)r * Tc + t;
                    #pragma unroll
                    for (int j = 0; j < 2; ++j) {
                        int n = c0 + j;
                        if (n < FCOUT) {
                            float v = fmaxf(a[half * 2 + j] + bias1[n], 0.0f);
                            if (n < Lc)            lab[bt * Lc + n]        = v * mask;
                            else if (n < Lc + Hc)  top[bt * Hc + (n - Lc)] = v * mask;
                            else if (n == Lc + Hc) temp[bt]                = expf(v) * mask;
                            else                   stop[bt]                = sigmoidf_(v) * mask;
                        }
                    }
                }
            }
        }
    }
}

// ---------------- K4: pointwise LSTM cell update -------------------------
__global__ __launch_bounds__(256) void lstm_pointwise() {
    int idx = blockIdx.x * 256 + threadIdx.x;     // B*H
    int r = idx >> 10, n = idx & 1023;
    size_t gi = (size_t)r * 4096 + n;
    float iv = g_gates[gi]        + g_base[gi];
    float fv = g_gates[gi + 1024] + g_base[gi + 1024];
    float gv = g_gates[gi + 2048] + g_base[gi + 2048];
    float ov = g_gates[gi + 3072] + g_base[gi + 3072];
    float m = sigmoidf_(fv) * g_m[idx] + sigmoidf_(iv) * tanhf(gv);
    g_m[idx] = m;
    float h = sigmoidf_(ov) * tanhf(m);
    __nv_bfloat16 hh, hl;
    bf16split(h, hh, hl);
    g_h_hi[idx] = hh;
    g_h_lo[idx] = hl;
}

// ---------------- launch -------------------------------------------------
#define SMEM_MMA 122880

extern "C" void kernel_launch(void* const* d_in, const int* in_sizes, int n_in,
                              void* d_out, int out_size)
{
    const float* image  = (const float*)d_in[0];
    const float* label  = (const float*)d_in[1];
    const int*   length = (const int*)  d_in[2];
    const float* W_h    = (const float*)d_in[3];
    const float* b_h    = (const float*)d_in[4];
    const float* W_m    = (const float*)d_in[5];
    const float* b_m    = (const float*)d_in[6];
    const float* W_ih   = (const float*)d_in[7];
    const float* W_hh   = (const float*)d_in[8];
    const float* b_ih   = (const float*)d_in[9];
    const float* b_hh   = (const float*)d_in[10];
    const float* W_fc   = (const float*)d_in[11];
    const float* b_fc   = (const float*)d_in[12];
    float* out = (float*)d_out;

    static bool attr_done = false;
    if (!attr_done) {
        cudaFuncSetAttribute(mma_big<0>, cudaFuncAttributeMaxDynamicSharedMemorySize, SMEM_MMA);
        cudaFuncSetAttribute(mma_big<1>, cudaFuncAttributeMaxDynamicSharedMemorySize, SMEM_MMA);
        cudaFuncSetAttribute(mma_big<2>, cudaFuncAttributeMaxDynamicSharedMemorySize, SMEM_MMA);
        cudaFuncSetAttribute(mma_big<3>, cudaFuncAttributeMaxDynamicSharedMemorySize, SMEM_MMA);
        cudaFuncSetAttribute(mma_big<4>, cudaFuncAttributeMaxDynamicSharedMemorySize, SMEM_MMA);
        attr_done = true;
    }

    mean_split<<<(Bb * Ec) / 256, 256>>>(image);

    auto nblk = [](int total) { return (total + 255) / 256; };
    split_kernel<<<nblk(1024*1024), 256>>>(W_h,  1024, 0,    1024, 1024, 1024*1024, 0);
    split_kernel<<<nblk(1024*1024), 256>>>(W_m,  1024, 0,    1024, 1024, 1024*1024, 1);
    split_kernel<<<nblk(4096*1024), 256>>>(W_ih, 1152, 0,    1024, 4096, 4096*1024, 2);
    split_kernel<<<nblk(4096*128),  256>>>(W_ih, 1152, 1024, 128,  4096, 4096*128,  3);
    split_kernel<<<nblk(4096*1024), 256>>>(W_hh, 1024, 0,    1024, 4096, 4096*1024, 4);
    split_kernel<<<nblk(FCPAD*1024),256>>>(W_fc, 1024, 0,    1024, FCOUT, FCPAD*1024, 5);
    split_kernel<<<nblk(Bb*Tc*Lc),  256>>>(label, Lc,  0,    Lc,   Bb*Tc, Bb*Tc*Lc,  6);

    // base = im@Wih^T + b_ih + b_hh ; h0 = tanh(im@Wh^T + b_h) ; m0 = tanh(im@Wm^T + b_m)
    mma_big<1><<<dim3(32, 4), 128, SMEM_MMA>>>(b_ih, b_hh, nullptr, nullptr, 0);
    mma_big<2><<<dim3(8, 4),  128, SMEM_MMA>>>(b_h, nullptr, nullptr, nullptr, 0);
    mma_big<3><<<dim3(8, 4),  128, SMEM_MMA>>>(b_m, nullptr, nullptr, nullptr, 0);

    for (int t = 0; t < Tc; ++t) {
        mma_big<0><<<dim3(32, 4), 128, SMEM_MMA>>>(nullptr, nullptr, nullptr, nullptr, t);
        lstm_pointwise<<<(Bb * Hc) / 256, 256>>>();
        mma_big<4><<<dim3(10, 4), 128, SMEM_MMA>>>(b_fc, nullptr, length, out, t);
    }
}

// round 7
// speedup vs baseline: 2.4995x; 1.3533x over previous
#include <cuda_runtime.h>
#include <cuda_bf16.h>
#include <math.h>
#include <stdint.h>

#define Bb    256
#define HWc   196
#define Ec    1024
#define Hc    1024
#define Lc    128
#define Tc    48
#define FCOUT 1154
#define FCPAD 1280   // 20 * 64

// ---------------- device-global scratch (allocation-free) ----------------
__device__ float g_m[Bb * Hc];
__device__ float g_base[Bb * 4 * Hc];
__device__ float g_gates[Bb * 4 * Hc];
__device__ __nv_bfloat16 g_h_hi[Bb * Hc],  g_h_lo[Bb * Hc];
__device__ __nv_bfloat16 g_im_hi[Bb * Ec], g_im_lo[Bb * Ec];
__device__ __nv_bfloat16 g_Whh_hi[4096 * 1024], g_Whh_lo[4096 * 1024];
__device__ __nv_bfloat16 g_Wih_hi[4096 * 1024], g_Wih_lo[4096 * 1024];
__device__ __nv_bfloat16 g_Wlab_hi[4096 * 128], g_Wlab_lo[4096 * 128];
__device__ __nv_bfloat16 g_Wh_hi[1024 * 1024],  g_Wh_lo[1024 * 1024];
__device__ __nv_bfloat16 g_Wm_hi[1024 * 1024],  g_Wm_lo[1024 * 1024];
__device__ __nv_bfloat16 g_Wfc_hi[FCPAD * 1024], g_Wfc_lo[FCPAD * 1024];
__device__ __nv_bfloat16 g_lab_hi[Bb * Tc * Lc], g_lab_lo[Bb * Tc * Lc];

// ---------------- helpers ----------------
__device__ __forceinline__ float sigmoidf_(float x) { return 1.0f / (1.0f + expf(-x)); }

__device__ __forceinline__ void bf16split(float v, __nv_bfloat16& h, __nv_bfloat16& l) {
    h = __float2bfloat16(v);
    l = __float2bfloat16(v - __bfloat162float(h));
}
__device__ __forceinline__ uint32_t smem_u32(const void* p) {
    return (uint32_t)__cvta_generic_to_shared(p);
}
__device__ __forceinline__ void cpasync16(uint32_t s, const void* g) {
    asm volatile("cp.async.cg.shared.global [%0], [%1], 16;\n" :: "r"(s), "l"(g) : "memory");
}
#define CP_COMMIT() asm volatile("cp.async.commit_group;\n" ::: "memory")
#define CP_WAIT2()  asm volatile("cp.async.wait_group 2;\n" ::: "memory")

__device__ __forceinline__ void ldsm4(uint32_t* r, uint32_t a) {
    asm volatile("ldmatrix.sync.aligned.m8n8.x4.shared.b16 {%0,%1,%2,%3}, [%4];"
        : "=r"(r[0]), "=r"(r[1]), "=r"(r[2]), "=r"(r[3]) : "r"(a));
}
__device__ __forceinline__ void ldsm2(uint32_t* r, uint32_t a) {
    asm volatile("ldmatrix.sync.aligned.m8n8.x2.shared.b16 {%0,%1}, [%2];"
        : "=r"(r[0]), "=r"(r[1]) : "r"(a));
}
__device__ __forceinline__ void mma_bf16(float* c, const uint32_t* a, const uint32_t* b) {
    asm volatile("mma.sync.aligned.m16n8k16.row.col.f32.bf16.bf16.f32 "
        "{%0,%1,%2,%3}, {%4,%5,%6,%7}, {%8,%9}, {%0,%1,%2,%3};"
        : "+f"(c[0]), "+f"(c[1]), "+f"(c[2]), "+f"(c[3])
        : "r"(a[0]), "r"(a[1]), "r"(a[2]), "r"(a[3]), "r"(b[0]), "r"(b[1]));
}

// ---------------- K1: mean + split ----------------
__global__ __launch_bounds__(256) void mean_split(const float* __restrict__ img) {
    int idx = blockIdx.x * 256 + threadIdx.x;   // B*E
    int b = idx >> 10, e = idx & 1023;
    const float* p = img + (size_t)b * HWc * Ec + e;
    float s = 0.0f;
    #pragma unroll 7
    for (int hw = 0; hw < HWc; ++hw) s += p[(size_t)hw * Ec];
    __nv_bfloat16 h, l;
    bf16split(s * (1.0f / HWc), h, l);
    g_im_hi[idx] = h; g_im_lo[idx] = l;
}

// ---------------- K2: fp32 -> bf16 hi/lo split (padded rows zeroed) ------
__global__ __launch_bounds__(256) void split_kernel(
    const float* __restrict__ in, int ld, int c0, int cols,
    int rows_valid, int total, int which)
{
    int idx = blockIdx.x * 256 + threadIdx.x;
    if (idx >= total) return;
    int r = idx / cols, c = idx % cols;
    float v = (r < rows_valid) ? in[(size_t)r * ld + c0 + c] : 0.0f;
    __nv_bfloat16 h, l;
    bf16split(v, h, l);
    __nv_bfloat16 *ph, *pl;
    switch (which) {
        case 0: ph = g_Wh_hi;  pl = g_Wh_lo;  break;
        case 1: ph = g_Wm_hi;  pl = g_Wm_lo;  break;
        case 2: ph = g_Wih_hi; pl = g_Wih_lo; break;
        case 3: ph = g_Wlab_hi;pl = g_Wlab_lo;break;
        case 4: ph = g_Whh_hi; pl = g_Whh_lo; break;
        case 5: ph = g_Wfc_hi; pl = g_Wfc_lo; break;
        default:ph = g_lab_hi; pl = g_lab_lo; break;
    }
    ph[idx] = h; pl[idx] = l;
}

// ---------------- K3: bf16x2 3-term tensor-core GEMM ---------------------
// CTA tile 64x64, 128 threads (4 warps, warp m32 x n32, 2x2 layout).
// 4-stage cp.async pipeline; smem/stage: Ahi|Alo|Bhi|Blo @ 5120 each = 20480.
// Total smem 81920 -> 2 CTAs/SM (2 warps per SMSP).
// MODE 0: gates  A=h(+label tail, K=1152) B=Whh/Wlab  -> g_gates (raw fp32)
// MODE 1: base   A=im B=Wih  (+b_ih+b_hh)             -> g_base
// MODE 2: h0     A=im B=Wh   tanh                     -> g_h hi/lo
// MODE 3: m0     A=im B=Wm   tanh                     -> g_m
// MODE 4: fc     A=h  B=Wfc  relu/exp/sigmoid/mask    -> out slices
template<int MODE>
__global__ void __launch_bounds__(128, 2) mma_big(
    const float* __restrict__ bias1, const float* __restrict__ bias2,
    const int* __restrict__ length, float* __restrict__ out, int t)
{
    constexpr int K   = (MODE == 0) ? 1152 : 1024;
    constexpr int NIT = K / 32;
    extern __shared__ char smem[];
    const uint32_t smb = smem_u32(smem);

    const int tid = threadIdx.x, lane = tid & 31, w = tid >> 5;
    const int bm0 = blockIdx.y * 64, bn0 = blockIdx.x * 64;

    float acc[2][4][4];
    #pragma unroll
    for (int a = 0; a < 2; ++a)
        #pragma unroll
        for (int b = 0; b < 4; ++b)
            #pragma unroll
            for (int c = 0; c < 4; ++c) acc[a][b][c] = 0.0f;

    auto load_stage = [&](int st, int k0) {
        uint32_t sb = smb + (uint32_t)st * 20480u;
        #pragma unroll
        for (int s = 0; s < 2; ++s) {                 // A: 64 rows x 4 chunks
            int slot = tid + s * 128;
            int r = slot >> 2, ch = slot & 3, k = k0 + ch * 8;
            const __nv_bfloat16 *gh, *gl;
            if (MODE == 0 && k >= 1024) {
                size_t off = ((size_t)(bm0 + r) * Tc + t) * Lc + (k - 1024);
                gh = g_lab_hi + off; gl = g_lab_lo + off;
            } else {
                size_t off = (size_t)(bm0 + r) * 1024 + k;
                if (MODE == 0 || MODE == 4) { gh = g_h_hi + off;  gl = g_h_lo + off; }
                else                         { gh = g_im_hi + off; gl = g_im_lo + off; }
            }
            uint32_t so = (uint32_t)(r * 80 + ch * 16);
            cpasync16(sb + so, gh);
            cpasync16(sb + 5120u + so, gl);
        }
        #pragma unroll
        for (int s = 0; s < 2; ++s) {                 // B: 64 rows x 4 chunks
            int slot = tid + s * 128;
            int r = slot >> 2, ch = slot & 3, k = k0 + ch * 8;
            int gr = bn0 + r;
            const __nv_bfloat16 *gh, *gl;
            if (MODE == 0 && k >= 1024) {
                size_t off = (size_t)gr * 128 + (k - 1024);
                gh = g_Wlab_hi + off; gl = g_Wlab_lo + off;
            } else {
                size_t off = (size_t)gr * 1024 + k;
                if      (MODE == 0) { gh = g_Whh_hi + off; gl = g_Whh_lo + off; }
                else if (MODE == 1) { gh = g_Wih_hi + off; gl = g_Wih_lo + off; }
                else if (MODE == 2) { gh = g_Wh_hi + off;  gl = g_Wh_lo + off; }
                else if (MODE == 3) { gh = g_Wm_hi + off;  gl = g_Wm_lo + off; }
                else                { gh = g_Wfc_hi + off; gl = g_Wfc_lo + off; }
            }
            uint32_t so = (uint32_t)(r * 80 + ch * 16);
            cpasync16(sb + 10240u + so, gh);
            cpasync16(sb + 15360u + so, gl);
        }
    };

    load_stage(0, 0);  CP_COMMIT();
    load_stage(1, 32); CP_COMMIT();

    // ldmatrix offsets: A rows (w>>1)*32.., B rows (w&1)*32..
    const uint32_t aOff = (uint32_t)(((w >> 1) * 32 + (lane & 15)) * 80 + (lane >> 4) * 16);
    const uint32_t bOff = (uint32_t)(((w & 1) * 32 + (lane & 7)) * 80 + ((lane >> 3) & 1) * 16);

    for (int it = 0; it < NIT; ++it) {
        if (it + 2 < NIT) load_stage((it + 2) & 3, (it + 2) * 32);
        CP_COMMIT();
        CP_WAIT2();
        __syncthreads();
        uint32_t sb = smb + (uint32_t)(it & 3) * 20480u;
        #pragma unroll
        for (int kh = 0; kh < 2; ++kh) {
            uint32_t afh[2][4], afl[2][4], bfh[4][2], bfl[4][2];
            #pragma unroll
            for (int mi = 0; mi < 2; ++mi) {
                uint32_t ad = sb + aOff + (uint32_t)(mi * 1280 + kh * 32);
                ldsm4(afh[mi], ad);
                ldsm4(afl[mi], ad + 5120u);
            }
            #pragma unroll
            for (int ni = 0; ni < 4; ++ni) {
                uint32_t bd = sb + 10240u + bOff + (uint32_t)(ni * 640 + kh * 32);
                ldsm2(bfh[ni], bd);
                ldsm2(bfl[ni], bd + 5120u);
            }
            // term-major: 8 independent mma between same-acc touches
            #pragma unroll
            for (int mi = 0; mi < 2; ++mi)
                #pragma unroll
                for (int ni = 0; ni < 4; ++ni)
                    mma_bf16(acc[mi][ni], afh[mi], bfh[ni]);
            #pragma unroll
            for (int mi = 0; mi < 2; ++mi)
                #pragma unroll
                for (int ni = 0; ni < 4; ++ni)
                    mma_bf16(acc[mi][ni], afl[mi], bfh[ni]);
            #pragma unroll
            for (int mi = 0; mi < 2; ++mi)
                #pragma unroll
                for (int ni = 0; ni < 4; ++ni)
                    mma_bf16(acc[mi][ni], afh[mi], bfl[ni]);
        }
        __syncthreads();
    }

    // ---------------- epilogue ----------------
    #pragma unroll
    for (int mi = 0; mi < 2; ++mi) {
        int r0 = bm0 + (w >> 1) * 32 + mi * 16 + (lane >> 2);
        #pragma unroll
        for (int ni = 0; ni < 4; ++ni) {
            int c0 = bn0 + (w & 1) * 32 + ni * 8 + (lane & 3) * 2;
            float* a = acc[mi][ni];
            if (MODE == 0) {
                *(float2*)&g_gates[(size_t)r0 * 4096 + c0]       = make_float2(a[0], a[1]);
                *(float2*)&g_gates[(size_t)(r0 + 8) * 4096 + c0] = make_float2(a[2], a[3]);
            } else if (MODE == 1) {
                float b0 = bias1[c0] + bias2[c0], b1 = bias1[c0 + 1] + bias2[c0 + 1];
                *(float2*)&g_base[(size_t)r0 * 4096 + c0]       = make_float2(a[0] + b0, a[1] + b1);
                *(float2*)&g_base[(size_t)(r0 + 8) * 4096 + c0] = make_float2(a[2] + b0, a[3] + b1);
            } else if (MODE == 2 || MODE == 3) {
                float b0 = bias1[c0], b1 = bias1[c0 + 1];
                float v0 = tanhf(a[0] + b0), v1 = tanhf(a[1] + b1);
                float v2 = tanhf(a[2] + b0), v3 = tanhf(a[3] + b1);
                if (MODE == 2) {
                    __nv_bfloat16 h0, l0, h1, l1;
                    __nv_bfloat162 hh, ll;
                    bf16split(v0, h0, l0); bf16split(v1, h1, l1);
                    hh.x = h0; hh.y = h1; ll.x = l0; ll.y = l1;
                    *(__nv_bfloat162*)&g_h_hi[(size_t)r0 * 1024 + c0] = hh;
                    *(__nv_bfloat162*)&g_h_lo[(size_t)r0 * 1024 + c0] = ll;
                    bf16split(v2, h0, l0); bf16split(v3, h1, l1);
                    hh.x = h0; hh.y = h1; ll.x = l0; ll.y = l1;
                    *(__nv_bfloat162*)&g_h_hi[(size_t)(r0 + 8) * 1024 + c0] = hh;
                    *(__nv_bfloat162*)&g_h_lo[(size_t)(r0 + 8) * 1024 + c0] = ll;
                } else {
                    g_m[(size_t)r0 * 1024 + c0]           = v0;
                    g_m[(size_t)r0 * 1024 + c0 + 1]       = v1;
                    g_m[(size_t)(r0 + 8) * 1024 + c0]     = v2;
                    g_m[(size_t)(r0 + 8) * 1024 + c0 + 1] = v3;
                }
            } else {   // MODE 4: fc outputs
                float* lab  = out;
                float* top  = out  + (size_t)Bb * Tc * Lc;
                float* temp = top  + (size_t)Bb * Tc * Hc;
                float* stop = temp + (size_t)Bb * Tc;
                #pragma unroll
                for (int half = 0; half < 2; ++half) {
                    int r = r0 + half * 8;
                    float mask = (t < length[r]) ? 1.0f : 0.0f;
                    size_t bt = (size_t)r * Tc + t;
                    #pragma unroll
                    for (int j = 0; j < 2; ++j) {
                        int n = c0 + j;
                        if (n < FCOUT) {
                            float v = fmaxf(a[half * 2 + j] + bias1[n], 0.0f);
                            if (n < Lc)            lab[bt * Lc + n]        = v * mask;
                            else if (n < Lc + Hc)  top[bt * Hc + (n - Lc)] = v * mask;
                            else if (n == Lc + Hc) temp[bt]                = expf(v) * mask;
                            else                   stop[bt]                = sigmoidf_(v) * mask;
                        }
                    }
                }
            }
        }
    }
}

// ---------------- K4: pointwise LSTM cell update -------------------------
__global__ __launch_bounds__(256) void lstm_pointwise() {
    int idx = blockIdx.x * 256 + threadIdx.x;     // B*H
    int r = idx >> 10, n = idx & 1023;
    size_t gi = (size_t)r * 4096 + n;
    float iv = g_gates[gi]        + g_base[gi];
    float fv = g_gates[gi + 1024] + g_base[gi + 1024];
    float gv = g_gates[gi + 2048] + g_base[gi + 2048];
    float ov = g_gates[gi + 3072] + g_base[gi + 3072];
    float m = sigmoidf_(fv) * g_m[idx] + sigmoidf_(iv) * tanhf(gv);
    g_m[idx] = m;
    float h = sigmoidf_(ov) * tanhf(m);
    __nv_bfloat16 hh, hl;
    bf16split(h, hh, hl);
    g_h_hi[idx] = hh;
    g_h_lo[idx] = hl;
}

// ---------------- launch -------------------------------------------------
#define SMEM_MMA 81920

extern "C" void kernel_launch(void* const* d_in, const int* in_sizes, int n_in,
                              void* d_out, int out_size)
{
    const float* image  = (const float*)d_in[0];
    const float* label  = (const float*)d_in[1];
    const int*   length = (const int*)  d_in[2];
    const float* W_h    = (const float*)d_in[3];
    const float* b_h    = (const float*)d_in[4];
    const float* W_m    = (const float*)d_in[5];
    const float* b_m    = (const float*)d_in[6];
    const float* W_ih   = (const float*)d_in[7];
    const float* W_hh   = (const float*)d_in[8];
    const float* b_ih   = (const float*)d_in[9];
    const float* b_hh   = (const float*)d_in[10];
    const float* W_fc   = (const float*)d_in[11];
    const float* b_fc   = (const float*)d_in[12];
    float* out = (float*)d_out;

    static bool attr_done = false;
    if (!attr_done) {
        cudaFuncSetAttribute(mma_big<0>, cudaFuncAttributeMaxDynamicSharedMemorySize, SMEM_MMA);
        cudaFuncSetAttribute(mma_big<1>, cudaFuncAttributeMaxDynamicSharedMemorySize, SMEM_MMA);
        cudaFuncSetAttribute(mma_big<2>, cudaFuncAttributeMaxDynamicSharedMemorySize, SMEM_MMA);
        cudaFuncSetAttribute(mma_big<3>, cudaFuncAttributeMaxDynamicSharedMemorySize, SMEM_MMA);
        cudaFuncSetAttribute(mma_big<4>, cudaFuncAttributeMaxDynamicSharedMemorySize, SMEM_MMA);
        attr_done = true;
    }

    mean_split<<<(Bb * Ec) / 256, 256>>>(image);

    auto nblk = [](int total) { return (total + 255) / 256; };
    split_kernel<<<nblk(1024*1024), 256>>>(W_h,  1024, 0,    1024, 1024, 1024*1024, 0);
    split_kernel<<<nblk(1024*1024), 256>>>(W_m,  1024, 0,    1024, 1024, 1024*1024, 1);
    split_kernel<<<nblk(4096*1024), 256>>>(W_ih, 1152, 0,    1024, 4096, 4096*1024, 2);
    split_kernel<<<nblk(4096*128),  256>>>(W_ih, 1152, 1024, 128,  4096, 4096*128,  3);
    split_kernel<<<nblk(4096*1024), 256>>>(W_hh, 1024, 0,    1024, 4096, 4096*1024, 4);
    split_kernel<<<nblk(FCPAD*1024),256>>>(W_fc, 1024, 0,    1024, FCOUT, FCPAD*1024, 5);
    split_kernel<<<nblk(Bb*Tc*Lc),  256>>>(label, Lc,  0,    Lc,   Bb*Tc, Bb*Tc*Lc,  6);

    // base = im@Wih^T + b_ih + b_hh ; h0 = tanh(im@Wh^T + b_h) ; m0 = tanh(im@Wm^T + b_m)
    mma_big<1><<<dim3(64, 4), 128, SMEM_MMA>>>(b_ih, b_hh, nullptr, nullptr, 0);
    mma_big<2><<<dim3(16, 4), 128, SMEM_MMA>>>(b_h, nullptr, nullptr, nullptr, 0);
    mma_big<3><<<dim3(16, 4), 128, SMEM_MMA>>>(b_m, nullptr, nullptr, nullptr, 0);

    for (int t = 0; t < Tc; ++t) {
        mma_big<0><<<dim3(64, 4), 128, SMEM_MMA>>>(nullptr, nullptr, nullptr, nullptr, t);
        lstm_pointwise<<<(Bb * Hc) / 256, 256>>>();
        mma_big<4><<<dim3(20, 4), 128, SMEM_MMA>>>(b_fc, nullptr, length, out, t);
    }
}

// round 9
// speedup vs baseline: 2.6682x; 1.0675x over previous
#include <cuda_runtime.h>
#include <cuda_bf16.h>
#include <math.h>
#include <stdint.h>

#define Bb    256
#define HWc   196
#define Ec    1024
#define Hc    1024
#define Lc    128
#define Tc    48
#define FCOUT 1154
#define FCPAD 1280   // 20 * 64

// ---------------- device-global scratch (allocation-free) ----------------
__device__ float g_m[Bb * Hc];
__device__ float g_base[Bb * 4 * Hc];
__device__ __nv_bfloat16 g_h_hi[Bb * Hc],  g_h_lo[Bb * Hc];
__device__ __nv_bfloat16 g_im_hi[Bb * Ec], g_im_lo[Bb * Ec];
__device__ __nv_bfloat16 g_Whh_hi[4096 * 1024], g_Whh_lo[4096 * 1024];
__device__ __nv_bfloat16 g_Wih_hi[4096 * 1024], g_Wih_lo[4096 * 1024];
__device__ __nv_bfloat16 g_Wlab_hi[4096 * 128], g_Wlab_lo[4096 * 128];
__device__ __nv_bfloat16 g_Wh_hi[1024 * 1024],  g_Wh_lo[1024 * 1024];
__device__ __nv_bfloat16 g_Wm_hi[1024 * 1024],  g_Wm_lo[1024 * 1024];
__device__ __nv_bfloat16 g_Wfc_hi[FCPAD * 1024], g_Wfc_lo[FCPAD * 1024];
__device__ __nv_bfloat16 g_lab_hi[Bb * Tc * Lc], g_lab_lo[Bb * Tc * Lc];

// ---------------- helpers ----------------
__device__ __forceinline__ float sigmoidf_(float x) { return 1.0f / (1.0f + expf(-x)); }

__device__ __forceinline__ void bf16split(float v, __nv_bfloat16& h, __nv_bfloat16& l) {
    h = __float2bfloat16(v);
    l = __float2bfloat16(v - __bfloat162float(h));
}
__device__ __forceinline__ uint32_t smem_u32(const void* p) {
    return (uint32_t)__cvta_generic_to_shared(p);
}
__device__ __forceinline__ void cpasync16(uint32_t s, const void* g) {
    asm volatile("cp.async.cg.shared.global [%0], [%1], 16;\n" :: "r"(s), "l"(g) : "memory");
}
#define CP_COMMIT() asm volatile("cp.async.commit_group;\n" ::: "memory")
#define CP_WAIT2()  asm volatile("cp.async.wait_group 2;\n" ::: "memory")

__device__ __forceinline__ void ldsm4(uint32_t* r, uint32_t a) {
    asm volatile("ldmatrix.sync.aligned.m8n8.x4.shared.b16 {%0,%1,%2,%3}, [%4];"
        : "=r"(r[0]), "=r"(r[1]), "=r"(r[2]), "=r"(r[3]) : "r"(a));
}
__device__ __forceinline__ void ldsm2(uint32_t* r, uint32_t a) {
    asm volatile("ldmatrix.sync.aligned.m8n8.x2.shared.b16 {%0,%1}, [%2];"
        : "=r"(r[0]), "=r"(r[1]) : "r"(a));
}
__device__ __forceinline__ void mma_bf16(float* c, const uint32_t* a, const uint32_t* b) {
    asm volatile("mma.sync.aligned.m16n8k16.row.col.f32.bf16.bf16.f32 "
        "{%0,%1,%2,%3}, {%4,%5,%6,%7}, {%8,%9}, {%0,%1,%2,%3};"
        : "+f"(c[0]), "+f"(c[1]), "+f"(c[2]), "+f"(c[3])
        : "r"(a[0]), "r"(a[1]), "r"(a[2]), "r"(a[3]), "r"(b[0]), "r"(b[1]));
}

// ---------------- K1: mean + split ----------------
__global__ __launch_bounds__(256) void mean_split(const float* __restrict__ img) {
    int idx = blockIdx.x * 256 + threadIdx.x;   // B*E
    int b = idx >> 10, e = idx & 1023;
    const float* p = img + (size_t)b * HWc * Ec + e;
    float s = 0.0f;
    #pragma unroll 7
    for (int hw = 0; hw < HWc; ++hw) s += p[(size_t)hw * Ec];
    __nv_bfloat16 h, l;
    bf16split(s * (1.0f / HWc), h, l);
    g_im_hi[idx] = h; g_im_lo[idx] = l;
}

// ---------------- K2: fp32 -> bf16 hi/lo split (padded rows zeroed) ------
__global__ __launch_bounds__(256) void split_kernel(
    const float* __restrict__ in, int ld, int c0, int cols,
    int rows_valid, int total, int which)
{
    int idx = blockIdx.x * 256 + threadIdx.x;
    if (idx >= total) return;
    int r = idx / cols, c = idx % cols;
    float v = (r < rows_valid) ? in[(size_t)r * ld + c0 + c] : 0.0f;
    __nv_bfloat16 h, l;
    bf16split(v, h, l);
    __nv_bfloat16 *ph, *pl;
    switch (which) {
        case 0: ph = g_Wh_hi;  pl = g_Wh_lo;  break;
        case 1: ph = g_Wm_hi;  pl = g_Wm_lo;  break;
        case 2: ph = g_Wih_hi; pl = g_Wih_lo; break;
        case 3: ph = g_Wlab_hi;pl = g_Wlab_lo;break;
        case 4: ph = g_Whh_hi; pl = g_Whh_lo; break;
        case 5: ph = g_Wfc_hi; pl = g_Wfc_lo; break;
        default:ph = g_lab_hi; pl = g_lab_lo; break;
    }
    ph[idx] = h; pl[idx] = l;
}

// ---------------- K3: bf16x2 3-term mma.sync GEMM ------------------------
// CTA tile 64x64, 128 threads (4 warps, warp m32 x n32), 4-stage cp.async.
// MODE 1: base = im@Wih^T + b_ih + b_hh        -> g_base
// MODE 2: h0 = tanh(im@Wh^T + b_h)             -> g_h hi/lo
// MODE 3: m0 = tanh(im@Wm^T + b_m)             -> g_m
// MODE 4: fc = h@Wfc^T + b_fc, activations+mask-> out slices (length skip)
template<int MODE>
__global__ void __launch_bounds__(128, 2) mma_big(
    const float* __restrict__ bias1, const float* __restrict__ bias2,
    const int* __restrict__ length, float* __restrict__ out, int t)
{
    constexpr int NIT = 1024 / 32;
    extern __shared__ char smem[];
    const uint32_t smb = smem_u32(smem);

    const int tid = threadIdx.x, lane = tid & 31, w = tid >> 5;
    const int bm0 = blockIdx.y * 64, bn0 = blockIdx.x * 64;

    if (MODE == 4) {
        // rows bm0..bm0+63 all masked (length sorted descending) -> zero-fill
        if (t >= length[bm0]) {
            float* lab  = out;
            float* top  = out  + (size_t)Bb * Tc * Lc;
            float* temp = top  + (size_t)Bb * Tc * Hc;
            float* stop = temp + (size_t)Bb * Tc;
            int r = tid & 63, ch = (tid >> 6) * 32;
            size_t bt = (size_t)(bm0 + r) * Tc + t;
            #pragma unroll 8
            for (int j = 0; j < 32; ++j) {
                int n = bn0 + ch + j;
                if (n < FCOUT) {
                    if (n < Lc)            lab[bt * Lc + n]        = 0.0f;
                    else if (n < Lc + Hc)  top[bt * Hc + (n - Lc)] = 0.0f;
                    else if (n == Lc + Hc) temp[bt]                = 0.0f;
                    else                   stop[bt]                = 0.0f;
                }
            }
            return;
        }
    }

    float acc[2][4][4];
    #pragma unroll
    for (int a = 0; a < 2; ++a)
        #pragma unroll
        for (int b = 0; b < 4; ++b)
            #pragma unroll
            for (int c = 0; c < 4; ++c) acc[a][b][c] = 0.0f;

    auto load_stage = [&](int st, int k0) {
        uint32_t sb = smb + (uint32_t)st * 20480u;
        #pragma unroll
        for (int s = 0; s < 2; ++s) {
            int slot = tid + s * 128;
            int r = slot >> 2, ch = slot & 3, k = k0 + ch * 8;
            size_t off = (size_t)(bm0 + r) * 1024 + k;
            const __nv_bfloat16 *ah, *al;
            if (MODE == 4) { ah = g_h_hi + off;  al = g_h_lo + off; }
            else           { ah = g_im_hi + off; al = g_im_lo + off; }
            uint32_t so = (uint32_t)(r * 80 + ch * 16);
            cpasync16(sb + so, ah);
            cpasync16(sb + 5120u + so, al);
        }
        #pragma unroll
        for (int s = 0; s < 2; ++s) {
            int slot = tid + s * 128;
            int r = slot >> 2, ch = slot & 3, k = k0 + ch * 8;
            size_t off = (size_t)(bn0 + r) * 1024 + k;
            const __nv_bfloat16 *gh, *gl;
            if      (MODE == 1) { gh = g_Wih_hi + off; gl = g_Wih_lo + off; }
            else if (MODE == 2) { gh = g_Wh_hi + off;  gl = g_Wh_lo + off; }
            else if (MODE == 3) { gh = g_Wm_hi + off;  gl = g_Wm_lo + off; }
            else                { gh = g_Wfc_hi + off; gl = g_Wfc_lo + off; }
            uint32_t so = (uint32_t)(r * 80 + ch * 16);
            cpasync16(sb + 10240u + so, gh);
            cpasync16(sb + 15360u + so, gl);
        }
    };

    load_stage(0, 0);  CP_COMMIT();
    load_stage(1, 32); CP_COMMIT();

    const uint32_t aOff = (uint32_t)(((w >> 1) * 32 + (lane & 15)) * 80 + (lane >> 4) * 16);
    const uint32_t bOff = (uint32_t)(((w & 1) * 32 + (lane & 7)) * 80 + ((lane >> 3) & 1) * 16);

    for (int it = 0; it < NIT; ++it) {
        if (it + 2 < NIT) load_stage((it + 2) & 3, (it + 2) * 32);
        CP_COMMIT();
        CP_WAIT2();
        __syncthreads();
        uint32_t sb = smb + (uint32_t)(it & 3) * 20480u;
        #pragma unroll
        for (int kh = 0; kh < 2; ++kh) {
            uint32_t afh[2][4], afl[2][4], bfh[4][2], bfl[4][2];
            #pragma unroll
            for (int mi = 0; mi < 2; ++mi) {
                uint32_t ad = sb + aOff + (uint32_t)(mi * 1280 + kh * 32);
                ldsm4(afh[mi], ad);
                ldsm4(afl[mi], ad + 5120u);
            }
            #pragma unroll
            for (int ni = 0; ni < 4; ++ni) {
                uint32_t bd = sb + 10240u + bOff + (uint32_t)(ni * 640 + kh * 32);
                ldsm2(bfh[ni], bd);
                ldsm2(bfl[ni], bd + 5120u);
            }
            #pragma unroll
            for (int mi = 0; mi < 2; ++mi)
                #pragma unroll
                for (int ni = 0; ni < 4; ++ni)
                    mma_bf16(acc[mi][ni], afh[mi], bfh[ni]);
            #pragma unroll
            for (int mi = 0; mi < 2; ++mi)
                #pragma unroll
                for (int ni = 0; ni < 4; ++ni)
                    mma_bf16(acc[mi][ni], afl[mi], bfh[ni]);
            #pragma unroll
            for (int mi = 0; mi < 2; ++mi)
                #pragma unroll
                for (int ni = 0; ni < 4; ++ni)
                    mma_bf16(acc[mi][ni], afh[mi], bfl[ni]);
        }
        __syncthreads();
    }

    #pragma unroll
    for (int mi = 0; mi < 2; ++mi) {
        int r0 = bm0 + (w >> 1) * 32 + mi * 16 + (lane >> 2);
        #pragma unroll
        for (int ni = 0; ni < 4; ++ni) {
            int c0 = bn0 + (w & 1) * 32 + ni * 8 + (lane & 3) * 2;
            float* a = acc[mi][ni];
            if (MODE == 1) {
                float b0 = bias1[c0] + bias2[c0], b1 = bias1[c0 + 1] + bias2[c0 + 1];
                *(float2*)&g_base[(size_t)r0 * 4096 + c0]       = make_float2(a[0] + b0, a[1] + b1);
                *(float2*)&g_base[(size_t)(r0 + 8) * 4096 + c0] = make_float2(a[2] + b0, a[3] + b1);
            } else if (MODE == 2 || MODE == 3) {
                float b0 = bias1[c0], b1 = bias1[c0 + 1];
                float v0 = tanhf(a[0] + b0), v1 = tanhf(a[1] + b1);
                float v2 = tanhf(a[2] + b0), v3 = tanhf(a[3] + b1);
                if (MODE == 2) {
                    __nv_bfloat16 h0, l0, h1, l1;
                    __nv_bfloat162 hh, ll;
                    bf16split(v0, h0, l0); bf16split(v1, h1, l1);
                    hh.x = h0; hh.y = h1; ll.x = l0; ll.y = l1;
                    *(__nv_bfloat162*)&g_h_hi[(size_t)r0 * 1024 + c0] = hh;
                    *(__nv_bfloat162*)&g_h_lo[(size_t)r0 * 1024 + c0] = ll;
                    bf16split(v2, h0, l0); bf16split(v3, h1, l1);
                    hh.x = h0; hh.y = h1; ll.x = l0; ll.y = l1;
                    *(__nv_bfloat162*)&g_h_hi[(size_t)(r0 + 8) * 1024 + c0] = hh;
                    *(__nv_bfloat162*)&g_h_lo[(size_t)(r0 + 8) * 1024 + c0] = ll;
                } else {
                    g_m[(size_t)r0 * 1024 + c0]           = v0;
                    g_m[(size_t)r0 * 1024 + c0 + 1]       = v1;
                    g_m[(size_t)(r0 + 8) * 1024 + c0]     = v2;
                    g_m[(size_t)(r0 + 8) * 1024 + c0 + 1] = v3;
                }
            } else {   // MODE 4: fc outputs
                float* lab  = out;
                float* top  = out  + (size_t)Bb * Tc * Lc;
                float* temp = top  + (size_t)Bb * Tc * Hc;
                float* stop = temp + (size_t)Bb * Tc;
                #pragma unroll
                for (int half = 0; half < 2; ++half) {
                    int r = r0 + half * 8;
                    float mask = (t < length[r]) ? 1.0f : 0.0f;
                    size_t bt = (size_t)r * Tc + t;
                    #pragma unroll
                    for (int j = 0; j < 2; ++j) {
                        int n = c0 + j;
                        if (n < FCOUT) {
                            float v = fmaxf(a[half * 2 + j] + bias1[n], 0.0f);
                            if (n < Lc)            lab[bt * Lc + n]        = v * mask;
                            else if (n < Lc + Hc)  top[bt * Hc + (n - Lc)] = v * mask;
                            else if (n == Lc + Hc) temp[bt]                = expf(v) * mask;
                            else                   stop[bt]                = sigmoidf_(v) * mask;
                        }
                    }
                }
            }
        }
    }
}

// ---------------- K5: fused gates GEMM + LSTM cell -----------------------
// CTA tile: 64 rows x 64 cols where cols = [i|f|g|o] x 16 h-cols.
// B row r (0..63): gate = r>>4, h-col = bn0h + (r&15), global W row =
// gate*1024 + h-col. K = 1152 (h 1024 + label 128). After GEMM, stage tile
// to smem and apply the LSTM update in-place (no g_gates round trip).
// Skips entire CTA when t >= length[bm0] (rows dead for all future outputs).
__global__ void __launch_bounds__(128, 2) gates_fused(
    const int* __restrict__ length, int t)
{
    constexpr int NIT = 1152 / 32;   // 36
    extern __shared__ char smem[];
    const uint32_t smb = smem_u32(smem);

    const int tid = threadIdx.x, lane = tid & 31, w = tid >> 5;
    const int bm0 = blockIdx.y * 64;
    const int bn0h = blockIdx.x * 16;

    if (t >= length[bm0]) return;   // all 64 rows inactive from here on

    float acc[2][4][4];
    #pragma unroll
    for (int a = 0; a < 2; ++a)
        #pragma unroll
        for (int b = 0; b < 4; ++b)
            #pragma unroll
            for (int c = 0; c < 4; ++c) acc[a][b][c] = 0.0f;

    auto load_stage = [&](int st, int k0) {
        uint32_t sb = smb + (uint32_t)st * 20480u;
        #pragma unroll
        for (int s = 0; s < 2; ++s) {                 // A: h rows / label tail
            int slot = tid + s * 128;
            int r = slot >> 2, ch = slot & 3, k = k0 + ch * 8;
            const __nv_bfloat16 *ah, *al;
            if (k >= 1024) {
                size_t off = ((size_t)(bm0 + r) * Tc + t) * Lc + (k - 1024);
                ah = g_lab_hi + off; al = g_lab_lo + off;
            } else {
                size_t off = (size_t)(bm0 + r) * 1024 + k;
                ah = g_h_hi + off; al = g_h_lo + off;
            }
            uint32_t so = (uint32_t)(r * 80 + ch * 16);
            cpasync16(sb + so, ah);
            cpasync16(sb + 5120u + so, al);
        }
        #pragma unroll
        for (int s = 0; s < 2; ++s) {                 // B: gate-grouped rows
            int slot = tid + s * 128;
            int r = slot >> 2, ch = slot & 3, k = k0 + ch * 8;
            int grow = (r >> 4) * 1024 + bn0h + (r & 15);
            const __nv_bfloat16 *bh, *bl;
            if (k >= 1024) {
                size_t off = (size_t)grow * 128 + (k - 1024);
                bh = g_Wlab_hi + off; bl = g_Wlab_lo + off;
            } else {
                size_t off = (size_t)grow * 1024 + k;
                bh = g_Whh_hi + off; bl = g_Whh_lo + off;
            }
            uint32_t so = (uint32_t)(r * 80 + ch * 16);
            cpasync16(sb + 10240u + so, bh);
            cpasync16(sb + 15360u + so, bl);
        }
    };

    load_stage(0, 0);  CP_COMMIT();
    load_stage(1, 32); CP_COMMIT();

    const uint32_t aOff = (uint32_t)(((w >> 1) * 32 + (lane & 15)) * 80 + (lane >> 4) * 16);
    const uint32_t bOff = (uint32_t)(((w & 1) * 32 + (lane & 7)) * 80 + ((lane >> 3) & 1) * 16);

    for (int it = 0; it < NIT; ++it) {
        if (it + 2 < NIT) load_stage((it + 2) & 3, (it + 2) * 32);
        CP_COMMIT();
        CP_WAIT2();
        __syncthreads();
        uint32_t sb = smb + (uint32_t)(it & 3) * 20480u;
        #pragma unroll
        for (int kh = 0; kh < 2; ++kh) {
            uint32_t afh[2][4], afl[2][4], bfh[4][2], bfl[4][2];
            #pragma unroll
            for (int mi = 0; mi < 2; ++mi) {
                uint32_t ad = sb + aOff + (uint32_t)(mi * 1280 + kh * 32);
                ldsm4(afh[mi], ad);
                ldsm4(afl[mi], ad + 5120u);
            }
            #pragma unroll
            for (int ni = 0; ni < 4; ++ni) {
                uint32_t bd = sb + 10240u + bOff + (uint32_t)(ni * 640 + kh * 32);
                ldsm2(bfh[ni], bd);
                ldsm2(bfl[ni], bd + 5120u);
            }
            #pragma unroll
            for (int mi = 0; mi < 2; ++mi)
                #pragma unroll
                for (int ni = 0; ni < 4; ++ni)
                    mma_bf16(acc[mi][ni], afh[mi], bfh[ni]);
            #pragma unroll
            for (int mi = 0; mi < 2; ++mi)
                #pragma unroll
                for (int ni = 0; ni < 4; ++ni)
                    mma_bf16(acc[mi][ni], afl[mi], bfh[ni]);
            #pragma unroll
            for (int mi = 0; mi < 2; ++mi)
                #pragma unroll
                for (int ni = 0; ni < 4; ++ni)
                    mma_bf16(acc[mi][ni], afh[mi], bfl[ni]);
        }
        __syncthreads();
    }

    // ---- stage 64x64 gate tile to smem (stride 68 floats) ----
    float* stg = (float*)smem;
    #pragma unroll
    for (int mi = 0; mi < 2; ++mi) {
        int r0 = (w >> 1) * 32 + mi * 16 + (lane >> 2);
        #pragma unroll
        for (int ni = 0; ni < 4; ++ni) {
            int c0 = (w & 1) * 32 + ni * 8 + (lane & 3) * 2;
            float* a = acc[mi][ni];
            *(float2*)&stg[r0 * 68 + c0]       = make_float2(a[0], a[1]);
            *(float2*)&stg[(r0 + 8) * 68 + c0] = make_float2(a[2], a[3]);
        }
    }
    __syncthreads();

    // ---- LSTM cell update: 128 threads x 8 rows x 1 h-col ----
    {
        int nl = tid & 15;          // h-col within block (0..15)
        int rg = tid >> 4;          // row group (0..7)
        int n = bn0h + nl;
        #pragma unroll
        for (int j = 0; j < 8; ++j) {
            int r = rg * 8 + j;
            int row = bm0 + r;
            float iv = stg[r * 68 + nl];
            float fv = stg[r * 68 + 16 + nl];
            float gv = stg[r * 68 + 32 + nl];
            float ov = stg[r * 68 + 48 + nl];
            size_t bidx = (size_t)row * 4096;
            iv += g_base[bidx + n];
            fv += g_base[bidx + 1024 + n];
            gv += g_base[bidx + 2048 + n];
            ov += g_base[bidx + 3072 + n];
            size_t hidx = (size_t)row * 1024 + n;
            float m = sigmoidf_(fv) * g_m[hidx] + sigmoidf_(iv) * tanhf(gv);
            g_m[hidx] = m;
            float h = sigmoidf_(ov) * tanhf(m);
            __nv_bfloat16 hh, hl;
            bf16split(h, hh, hl);
            g_h_hi[hidx] = hh;
            g_h_lo[hidx] = hl;
        }
    }
}

// ---------------- launch -------------------------------------------------
#define SMEM_MMA 81920

extern "C" void kernel_launch(void* const* d_in, const int* in_sizes, int n_in,
                              void* d_out, int out_size)
{
    const float* image  = (const float*)d_in[0];
    const float* label  = (const float*)d_in[1];
    const int*   length = (const int*)  d_in[2];
    const float* W_h    = (const float*)d_in[3];
    const float* b_h    = (const float*)d_in[4];
    const float* W_m    = (const float*)d_in[5];
    const float* b_m    = (const float*)d_in[6];
    const float* W_ih   = (const float*)d_in[7];
    const float* W_hh   = (const float*)d_in[8];
    const float* b_ih   = (const float*)d_in[9];
    const float* b_hh   = (const float*)d_in[10];
    const float* W_fc   = (const float*)d_in[11];
    const float* b_fc   = (const float*)d_in[12];
    float* out = (float*)d_out;

    static bool attr_done = false;
    if (!attr_done) {
        cudaFuncSetAttribute(mma_big<1>, cudaFuncAttributeMaxDynamicSharedMemorySize, SMEM_MMA);
        cudaFuncSetAttribute(mma_big<2>, cudaFuncAttributeMaxDynamicSharedMemorySize, SMEM_MMA);
        cudaFuncSetAttribute(mma_big<3>, cudaFuncAttributeMaxDynamicSharedMemorySize, SMEM_MMA);
        cudaFuncSetAttribute(mma_big<4>, cudaFuncAttributeMaxDynamicSharedMemorySize, SMEM_MMA);
        cudaFuncSetAttribute(gates_fused, cudaFuncAttributeMaxDynamicSharedMemorySize, SMEM_MMA);
        attr_done = true;
    }

    mean_split<<<(Bb * Ec) / 256, 256>>>(image);

    auto nblk = [](int total) { return (total + 255) / 256; };
    split_kernel<<<nblk(1024*1024), 256>>>(W_h,  1024, 0,    1024, 1024, 1024*1024, 0);
    split_kernel<<<nblk(1024*1024), 256>>>(W_m,  1024, 0,    1024, 1024, 1024*1024, 1);
    split_kernel<<<nblk(4096*1024), 256>>>(W_ih, 1152, 0,    1024, 4096, 4096*1024, 2);
    split_kernel<<<nblk(4096*128),  256>>>(W_ih, 1152, 1024, 128,  4096, 4096*128,  3);
    split_kernel<<<nblk(4096*1024), 256>>>(W_hh, 1024, 0,    1024, 4096, 4096*1024, 4);
    split_kernel<<<nblk(FCPAD*1024),256>>>(W_fc, 1024, 0,    1024, FCOUT, FCPAD*1024, 5);
    split_kernel<<<nblk(Bb*Tc*Lc),  256>>>(label, Lc,  0,    Lc,   Bb*Tc, Bb*Tc*Lc,  6);

    // base = im@Wih^T + b_ih + b_hh ; h0 = tanh(im@Wh^T+b_h) ; m0 = tanh(im@Wm^T+b_m)
    mma_big<1><<<dim3(64, 4), 128, SMEM_MMA>>>(b_ih, b_hh, nullptr, nullptr, 0);
    mma_big<2><<<dim3(16, 4), 128, SMEM_MMA>>>(b_h, nullptr, nullptr, nullptr, 0);
    mma_big<3><<<dim3(16, 4), 128, SMEM_MMA>>>(b_m, nullptr, nullptr, nullptr, 0);

    for (int t = 0; t < Tc; ++t) {
        gates_fused<<<dim3(64, 4), 128, SMEM_MMA>>>(length, t);
        mma_big<4><<<dim3(20, 4), 128, SMEM_MMA>>>(b_fc, nullptr, length, out, t);
    }
}

// round 10
// speedup vs baseline: 3.5011x; 1.3122x over previous
#include <cuda_runtime.h>
#include <cuda_bf16.h>
#include <math.h>
#include <stdint.h>

#define Bb    256
#define HWc   196
#define Ec    1024
#define Hc    1024
#define Lc    128
#define Tc    48
#define FCOUT 1154
#define FCPAD 1280

// ---------------- device-global scratch (allocation-free) ----------------
__device__ float g_m[Bb * Hc];
__device__ float g_base[Bb * 4 * Hc];
__device__ __nv_bfloat16 g_h_hi[2][Bb * Hc], g_h_lo[2][Bb * Hc];   // ping-pong
__device__ __nv_bfloat16 g_im_hi[Bb * Ec], g_im_lo[Bb * Ec];
__device__ __nv_bfloat16 g_Whh_hi[4096 * 1024], g_Whh_lo[4096 * 1024];
__device__ __nv_bfloat16 g_Wih_hi[4096 * 1024], g_Wih_lo[4096 * 1024];
__device__ __nv_bfloat16 g_Wlab_hi[4096 * 128], g_Wlab_lo[4096 * 128];
__device__ __nv_bfloat16 g_Wh_hi[1024 * 1024],  g_Wh_lo[1024 * 1024];
__device__ __nv_bfloat16 g_Wm_hi[1024 * 1024],  g_Wm_lo[1024 * 1024];
__device__ __nv_bfloat16 g_Wfc_hi[FCPAD * 1024], g_Wfc_lo[FCPAD * 1024];
__device__ __nv_bfloat16 g_lab_hi[Bb * Tc * Lc], g_lab_lo[Bb * Tc * Lc];

// ---------------- helpers ----------------
__device__ __forceinline__ float sigmoidf_(float x) { return 1.0f / (1.0f + expf(-x)); }

__device__ __forceinline__ void bf16split(float v, __nv_bfloat16& h, __nv_bfloat16& l) {
    h = __float2bfloat16(v);
    l = __float2bfloat16(v - __bfloat162float(h));
}
__device__ __forceinline__ uint32_t smem_u32(const void* p) {
    return (uint32_t)__cvta_generic_to_shared(p);
}
__device__ __forceinline__ void cpasync16(uint32_t s, const void* g) {
    asm volatile("cp.async.cg.shared.global [%0], [%1], 16;\n" :: "r"(s), "l"(g) : "memory");
}
#define CP_COMMIT() asm volatile("cp.async.commit_group;\n" ::: "memory")
#define CP_WAIT2()  asm volatile("cp.async.wait_group 2;\n" ::: "memory")

__device__ __forceinline__ void ldsm4(uint32_t* r, uint32_t a) {
    asm volatile("ldmatrix.sync.aligned.m8n8.x4.shared.b16 {%0,%1,%2,%3}, [%4];"
        : "=r"(r[0]), "=r"(r[1]), "=r"(r[2]), "=r"(r[3]) : "r"(a));
}
__device__ __forceinline__ void ldsm2(uint32_t* r, uint32_t a) {
    asm volatile("ldmatrix.sync.aligned.m8n8.x2.shared.b16 {%0,%1}, [%2];"
        : "=r"(r[0]), "=r"(r[1]) : "r"(a));
}
__device__ __forceinline__ void mma_bf16(float* c, const uint32_t* a, const uint32_t* b) {
    asm volatile("mma.sync.aligned.m16n8k16.row.col.f32.bf16.bf16.f32 "
        "{%0,%1,%2,%3}, {%4,%5,%6,%7}, {%8,%9}, {%0,%1,%2,%3};"
        : "+f"(c[0]), "+f"(c[1]), "+f"(c[2]), "+f"(c[3])
        : "r"(a[0]), "r"(a[1]), "r"(a[2]), "r"(a[3]), "r"(b[0]), "r"(b[1]));
}

// ---------------- K1: mean + split ----------------
__global__ __launch_bounds__(256) void mean_split(const float* __restrict__ img) {
    int idx = blockIdx.x * 256 + threadIdx.x;
    int b = idx >> 10, e = idx & 1023;
    const float* p = img + (size_t)b * HWc * Ec + e;
    float s = 0.0f;
    #pragma unroll 7
    for (int hw = 0; hw < HWc; ++hw) s += p[(size_t)hw * Ec];
    __nv_bfloat16 h, l;
    bf16split(s * (1.0f / HWc), h, l);
    g_im_hi[idx] = h; g_im_lo[idx] = l;
}

// ---------------- K2: fp32 -> bf16 hi/lo split ----------------
__global__ __launch_bounds__(256) void split_kernel(
    const float* __restrict__ in, int ld, int c0, int cols,
    int rows_valid, int total, int which)
{
    int idx = blockIdx.x * 256 + threadIdx.x;
    if (idx >= total) return;
    int r = idx / cols, c = idx % cols;
    float v = (r < rows_valid) ? in[(size_t)r * ld + c0 + c] : 0.0f;
    __nv_bfloat16 h, l;
    bf16split(v, h, l);
    __nv_bfloat16 *ph, *pl;
    switch (which) {
        case 0: ph = g_Wh_hi;  pl = g_Wh_lo;  break;
        case 1: ph = g_Wm_hi;  pl = g_Wm_lo;  break;
        case 2: ph = g_Wih_hi; pl = g_Wih_lo; break;
        case 3: ph = g_Wlab_hi;pl = g_Wlab_lo;break;
        case 4: ph = g_Whh_hi; pl = g_Whh_lo; break;
        case 5: ph = g_Wfc_hi; pl = g_Wfc_lo; break;
        default:ph = g_lab_hi; pl = g_lab_lo; break;
    }
    ph[idx] = h; pl[idx] = l;
}

// ---------------- K3: setup GEMMs (mma.sync bf16x2 3-term) ---------------
// MODE 1: base = im@Wih^T + b_ih + b_hh ; MODE 2: h0 -> g_h[0] ; MODE 3: m0
template<int MODE>
__global__ void __launch_bounds__(128, 2) mma_big(
    const float* __restrict__ bias1, const float* __restrict__ bias2)
{
    constexpr int NIT = 1024 / 32;
    extern __shared__ char smem[];
    const uint32_t smb = smem_u32(smem);

    const int tid = threadIdx.x, lane = tid & 31, w = tid >> 5;
    const int bm0 = blockIdx.y * 64, bn0 = blockIdx.x * 64;

    float acc[2][4][4];
    #pragma unroll
    for (int a = 0; a < 2; ++a)
        #pragma unroll
        for (int b = 0; b < 4; ++b)
            #pragma unroll
            for (int c = 0; c < 4; ++c) acc[a][b][c] = 0.0f;

    auto load_stage = [&](int st, int k0) {
        uint32_t sb = smb + (uint32_t)st * 20480u;
        #pragma unroll
        for (int s = 0; s < 2; ++s) {
            int slot = tid + s * 128;
            int r = slot >> 2, ch = slot & 3, k = k0 + ch * 8;
            size_t off = (size_t)(bm0 + r) * 1024 + k;
            uint32_t so = (uint32_t)(r * 80 + ch * 16);
            cpasync16(sb + so, g_im_hi + off);
            cpasync16(sb + 5120u + so, g_im_lo + off);
        }
        #pragma unroll
        for (int s = 0; s < 2; ++s) {
            int slot = tid + s * 128;
            int r = slot >> 2, ch = slot & 3, k = k0 + ch * 8;
            size_t off = (size_t)(bn0 + r) * 1024 + k;
            const __nv_bfloat16 *gh, *gl;
            if      (MODE == 1) { gh = g_Wih_hi + off; gl = g_Wih_lo + off; }
            else if (MODE == 2) { gh = g_Wh_hi + off;  gl = g_Wh_lo + off; }
            else                { gh = g_Wm_hi + off;  gl = g_Wm_lo + off; }
            uint32_t so = (uint32_t)(r * 80 + ch * 16);
            cpasync16(sb + 10240u + so, gh);
            cpasync16(sb + 15360u + so, gl);
        }
    };

    load_stage(0, 0);  CP_COMMIT();
    load_stage(1, 32); CP_COMMIT();

    const uint32_t aOff = (uint32_t)(((w >> 1) * 32 + (lane & 15)) * 80 + (lane >> 4) * 16);
    const uint32_t bOff = (uint32_t)(((w & 1) * 32 + (lane & 7)) * 80 + ((lane >> 3) & 1) * 16);

    for (int it = 0; it < NIT; ++it) {
        if (it + 2 < NIT) load_stage((it + 2) & 3, (it + 2) * 32);
        CP_COMMIT();
        CP_WAIT2();
        __syncthreads();
        uint32_t sb = smb + (uint32_t)(it & 3) * 20480u;
        #pragma unroll
        for (int kh = 0; kh < 2; ++kh) {
            uint32_t afh[2][4], afl[2][4], bfh[4][2], bfl[4][2];
            #pragma unroll
            for (int mi = 0; mi < 2; ++mi) {
                uint32_t ad = sb + aOff + (uint32_t)(mi * 1280 + kh * 32);
                ldsm4(afh[mi], ad);
                ldsm4(afl[mi], ad + 5120u);
            }
            #pragma unroll
            for (int ni = 0; ni < 4; ++ni) {
                uint32_t bd = sb + 10240u + bOff + (uint32_t)(ni * 640 + kh * 32);
                ldsm2(bfh[ni], bd);
                ldsm2(bfl[ni], bd + 5120u);
            }
            #pragma unroll
            for (int mi = 0; mi < 2; ++mi)
                #pragma unroll
                for (int ni = 0; ni < 4; ++ni)
                    mma_bf16(acc[mi][ni], afh[mi], bfh[ni]);
            #pragma unroll
            for (int mi = 0; mi < 2; ++mi)
                #pragma unroll
                for (int ni = 0; ni < 4; ++ni)
                    mma_bf16(acc[mi][ni], afl[mi], bfh[ni]);
            #pragma unroll
            for (int mi = 0; mi < 2; ++mi)
                #pragma unroll
                for (int ni = 0; ni < 4; ++ni)
                    mma_bf16(acc[mi][ni], afh[mi], bfl[ni]);
        }
        __syncthreads();
    }

    #pragma unroll
    for (int mi = 0; mi < 2; ++mi) {
        int r0 = bm0 + (w >> 1) * 32 + mi * 16 + (lane >> 2);
        #pragma unroll
        for (int ni = 0; ni < 4; ++ni) {
            int c0 = bn0 + (w & 1) * 32 + ni * 8 + (lane & 3) * 2;
            float* a = acc[mi][ni];
            if (MODE == 1) {
                float b0 = bias1[c0] + bias2[c0], b1 = bias1[c0 + 1] + bias2[c0 + 1];
                *(float2*)&g_base[(size_t)r0 * 4096 + c0]       = make_float2(a[0] + b0, a[1] + b1);
                *(float2*)&g_base[(size_t)(r0 + 8) * 4096 + c0] = make_float2(a[2] + b0, a[3] + b1);
            } else {
                float b0 = bias1[c0], b1 = bias1[c0 + 1];
                float v0 = tanhf(a[0] + b0), v1 = tanhf(a[1] + b1);
                float v2 = tanhf(a[2] + b0), v3 = tanhf(a[3] + b1);
                if (MODE == 2) {
                    __nv_bfloat16 h0, l0, h1, l1;
                    __nv_bfloat162 hh, ll;
                    bf16split(v0, h0, l0); bf16split(v1, h1, l1);
                    hh.x = h0; hh.y = h1; ll.x = l0; ll.y = l1;
                    *(__nv_bfloat162*)&g_h_hi[0][(size_t)r0 * 1024 + c0] = hh;
                    *(__nv_bfloat162*)&g_h_lo[0][(size_t)r0 * 1024 + c0] = ll;
                    bf16split(v2, h0, l0); bf16split(v3, h1, l1);
                    hh.x = h0; hh.y = h1; ll.x = l0; ll.y = l1;
                    *(__nv_bfloat162*)&g_h_hi[0][(size_t)(r0 + 8) * 1024 + c0] = hh;
                    *(__nv_bfloat162*)&g_h_lo[0][(size_t)(r0 + 8) * 1024 + c0] = ll;
                } else {
                    g_m[(size_t)r0 * 1024 + c0]           = v0;
                    g_m[(size_t)r0 * 1024 + c0 + 1]       = v1;
                    g_m[(size_t)(r0 + 8) * 1024 + c0]     = v2;
                    g_m[(size_t)(r0 + 8) * 1024 + c0 + 1] = v3;
                }
            }
        }
    }
}

// ---------------- K4: fused step kernel ----------------------------------
// One launch per step t (t = 0..Tc):
//   blockIdx.x <  64 : GATES role, step t (skipped when t >= Tc or block dead)
//     gates tile 64 rows x [i|f|g|o]x16 h-cols, K=1152; LSTM cell epilogue.
//     reads h[t&1] (+label, base, m), writes h[(t+1)&1] + m.
//   blockIdx.x >= 64 : FC role, step tf = t-1 (skipped when tf < 0)
//     fc tile 64 rows x 64 out-cols, K=1024; act/mask epilogue -> out.
//     reads h[t&1] only. No buffer overlap with gates writes -> race-free.
__global__ void __launch_bounds__(128, 2) step_fused(
    const float* __restrict__ bfc, const int* __restrict__ length,
    float* __restrict__ out, int t)
{
    extern __shared__ char smem[];
    const uint32_t smb = smem_u32(smem);
    const int tid = threadIdx.x, lane = tid & 31, w = tid >> 5;
    const int bm0 = blockIdx.y * 64;
    const bool gates_role = (blockIdx.x < 64);
    const int tf = t - 1;

    int bn0h = 0, bn0f = 0, nit;
    if (gates_role) {
        if (t >= Tc) return;
        if (t >= length[bm0]) return;        // block fully dead (desc-sorted)
        bn0h = blockIdx.x * 16;
        nit = 36;
    } else {
        if (tf < 0) return;
        bn0f = (blockIdx.x - 64) * 64;
        nit = 32;
        if (tf >= length[bm0]) {             // zero-fill dead block outputs
            float* lab  = out;
            float* top  = out  + (size_t)Bb * Tc * Lc;
            float* temp = top  + (size_t)Bb * Tc * Hc;
            float* stop = temp + (size_t)Bb * Tc;
            int r = tid & 63, ch = (tid >> 6) * 32;
            size_t bt = (size_t)(bm0 + r) * Tc + tf;
            #pragma unroll 8
            for (int j = 0; j < 32; ++j) {
                int n = bn0f + ch + j;
                if (n < FCOUT) {
                    if (n < Lc)            lab[bt * Lc + n]        = 0.0f;
                    else if (n < Lc + Hc)  top[bt * Hc + (n - Lc)] = 0.0f;
                    else if (n == Lc + Hc) temp[bt]                = 0.0f;
                    else                   stop[bt]                = 0.0f;
                }
            }
            return;
        }
    }

    // both roles read buffer (t & 1): gates read h_t, fc reads h_{tf+1} = h_t
    const __nv_bfloat16* h_in_hi = g_h_hi[t & 1];
    const __nv_bfloat16* h_in_lo = g_h_lo[t & 1];

    float acc[2][4][4];
    #pragma unroll
    for (int a = 0; a < 2; ++a)
        #pragma unroll
        for (int b = 0; b < 4; ++b)
            #pragma unroll
            for (int c = 0; c < 4; ++c) acc[a][b][c] = 0.0f;

    auto load_stage = [&](int st, int k0) {
        uint32_t sb = smb + (uint32_t)st * 20480u;
        #pragma unroll
        for (int s = 0; s < 2; ++s) {                 // A tile
            int slot = tid + s * 128;
            int r = slot >> 2, ch = slot & 3, k = k0 + ch * 8;
            const __nv_bfloat16 *ah, *al;
            if (gates_role && k >= 1024) {
                size_t off = ((size_t)(bm0 + r) * Tc + t) * Lc + (k - 1024);
                ah = g_lab_hi + off; al = g_lab_lo + off;
            } else {
                size_t off = (size_t)(bm0 + r) * 1024 + k;
                ah = h_in_hi + off; al = h_in_lo + off;
            }
            uint32_t so = (uint32_t)(r * 80 + ch * 16);
            cpasync16(sb + so, ah);
            cpasync16(sb + 5120u + so, al);
        }
        #pragma unroll
        for (int s = 0; s < 2; ++s) {                 // B tile
            int slot = tid + s * 128;
            int r = slot >> 2, ch = slot & 3, k = k0 + ch * 8;
            const __nv_bfloat16 *bh, *bl;
            if (gates_role) {
                int grow = (r >> 4) * 1024 + bn0h + (r & 15);
                if (k >= 1024) {
                    size_t off = (size_t)grow * 128 + (k - 1024);
                    bh = g_Wlab_hi + off; bl = g_Wlab_lo + off;
                } else {
                    size_t off = (size_t)grow * 1024 + k;
                    bh = g_Whh_hi + off; bl = g_Whh_lo + off;
                }
            } else {
                size_t off = (size_t)(bn0f + r) * 1024 + k;
                bh = g_Wfc_hi + off; bl = g_Wfc_lo + off;
            }
            uint32_t so = (uint32_t)(r * 80 + ch * 16);
            cpasync16(sb + 10240u + so, bh);
            cpasync16(sb + 15360u + so, bl);
        }
    };

    load_stage(0, 0);  CP_COMMIT();
    load_stage(1, 32); CP_COMMIT();

    const uint32_t aOff = (uint32_t)(((w >> 1) * 32 + (lane & 15)) * 80 + (lane >> 4) * 16);
    const uint32_t bOff = (uint32_t)(((w & 1) * 32 + (lane & 7)) * 80 + ((lane >> 3) & 1) * 16);

    for (int it = 0; it < nit; ++it) {
        if (it + 2 < nit) load_stage((it + 2) & 3, (it + 2) * 32);
        CP_COMMIT();
        CP_WAIT2();
        __syncthreads();
        uint32_t sb = smb + (uint32_t)(it & 3) * 20480u;
        #pragma unroll
        for (int kh = 0; kh < 2; ++kh) {
            uint32_t afh[2][4], afl[2][4], bfh[4][2], bfl[4][2];
            #pragma unroll
            for (int mi = 0; mi < 2; ++mi) {
                uint32_t ad = sb + aOff + (uint32_t)(mi * 1280 + kh * 32);
                ldsm4(afh[mi], ad);
                ldsm4(afl[mi], ad + 5120u);
            }
            #pragma unroll
            for (int ni = 0; ni < 4; ++ni) {
                uint32_t bd = sb + 10240u + bOff + (uint32_t)(ni * 640 + kh * 32);
                ldsm2(bfh[ni], bd);
                ldsm2(bfl[ni], bd + 5120u);
            }
            #pragma unroll
            for (int mi = 0; mi < 2; ++mi)
                #pragma unroll
                for (int ni = 0; ni < 4; ++ni)
                    mma_bf16(acc[mi][ni], afh[mi], bfh[ni]);
            #pragma unroll
            for (int mi = 0; mi < 2; ++mi)
                #pragma unroll
                for (int ni = 0; ni < 4; ++ni)
                    mma_bf16(acc[mi][ni], afl[mi], bfh[ni]);
            #pragma unroll
            for (int mi = 0; mi < 2; ++mi)
                #pragma unroll
                for (int ni = 0; ni < 4; ++ni)
                    mma_bf16(acc[mi][ni], afh[mi], bfl[ni]);
        }
        __syncthreads();
    }

    if (gates_role) {
        // ---- stage 64x64 gate tile to smem (stride 68 floats) ----
        float* stg = (float*)smem;
        #pragma unroll
        for (int mi = 0; mi < 2; ++mi) {
            int r0 = (w >> 1) * 32 + mi * 16 + (lane >> 2);
            #pragma unroll
            for (int ni = 0; ni < 4; ++ni) {
                int c0 = (w & 1) * 32 + ni * 8 + (lane & 3) * 2;
                float* a = acc[mi][ni];
                *(float2*)&stg[r0 * 68 + c0]       = make_float2(a[0], a[1]);
                *(float2*)&stg[(r0 + 8) * 68 + c0] = make_float2(a[2], a[3]);
            }
        }
        __syncthreads();

        // ---- LSTM cell update (h ping-pong write) ----
        __nv_bfloat16* h_out_hi = g_h_hi[(t + 1) & 1];
        __nv_bfloat16* h_out_lo = g_h_lo[(t + 1) & 1];
        int nl = tid & 15;
        int rg = tid >> 4;
        int n = bn0h + nl;
        #pragma unroll
        for (int j = 0; j < 8; ++j) {
            int r = rg * 8 + j;
            int row = bm0 + r;
            float iv = stg[r * 68 + nl];
            float fv = stg[r * 68 + 16 + nl];
            float gv = stg[r * 68 + 32 + nl];
            float ov = stg[r * 68 + 48 + nl];
            size_t bidx = (size_t)row * 4096;
            iv += g_base[bidx + n];
            fv += g_base[bidx + 1024 + n];
            gv += g_base[bidx + 2048 + n];
            ov += g_base[bidx + 3072 + n];
            size_t hidx = (size_t)row * 1024 + n;
            float m = sigmoidf_(fv) * g_m[hidx] + sigmoidf_(iv) * tanhf(gv);
            g_m[hidx] = m;
            float h = sigmoidf_(ov) * tanhf(m);
            __nv_bfloat16 hh, hl;
            bf16split(h, hh, hl);
            h_out_hi[hidx] = hh;
            h_out_lo[hidx] = hl;
        }
    } else {
        // ---- fc epilogue for step tf ----
        float* lab  = out;
        float* top  = out  + (size_t)Bb * Tc * Lc;
        float* temp = top  + (size_t)Bb * Tc * Hc;
        float* stop = temp + (size_t)Bb * Tc;
        #pragma unroll
        for (int mi = 0; mi < 2; ++mi) {
            int r0 = bm0 + (w >> 1) * 32 + mi * 16 + (lane >> 2);
            #pragma unroll
            for (int ni = 0; ni < 4; ++ni) {
                int c0 = bn0f + (w & 1) * 32 + ni * 8 + (lane & 3) * 2;
                float* a = acc[mi][ni];
                #pragma unroll
                for (int half = 0; half < 2; ++half) {
                    int r = r0 + half * 8;
                    float mask = (tf < length[r]) ? 1.0f : 0.0f;
                    size_t bt = (size_t)r * Tc + tf;
                    #pragma unroll
                    for (int j = 0; j < 2; ++j) {
                        int n = c0 + j;
                        if (n < FCOUT) {
                            float v = fmaxf(a[half * 2 + j] + bfc[n], 0.0f);
                            if (n < Lc)            lab[bt * Lc + n]        = v * mask;
                            else if (n < Lc + Hc)  top[bt * Hc + (n - Lc)] = v * mask;
                            else if (n == Lc + Hc) temp[bt]                = expf(v) * mask;
                            else                   stop[bt]                = sigmoidf_(v) * mask;
                        }
                    }
                }
            }
        }
    }
}

// ---------------- launch -------------------------------------------------
#define SMEM_MMA 81920

extern "C" void kernel_launch(void* const* d_in, const int* in_sizes, int n_in,
                              void* d_out, int out_size)
{
    const float* image  = (const float*)d_in[0];
    const float* label  = (const float*)d_in[1];
    const int*   length = (const int*)  d_in[2];
    const float* W_h    = (const float*)d_in[3];
    const float* b_h    = (const float*)d_in[4];
    const float* W_m    = (const float*)d_in[5];
    const float* b_m    = (const float*)d_in[6];
    const float* W_ih   = (const float*)d_in[7];
    const float* W_hh   = (const float*)d_in[8];
    const float* b_ih   = (const float*)d_in[9];
    const float* b_hh   = (const float*)d_in[10];
    const float* W_fc   = (const float*)d_in[11];
    const float* b_fc   = (const float*)d_in[12];
    float* out = (float*)d_out;

    static bool attr_done = false;
    if (!attr_done) {
        cudaFuncSetAttribute(mma_big<1>, cudaFuncAttributeMaxDynamicSharedMemorySize, SMEM_MMA);
        cudaFuncSetAttribute(mma_big<2>, cudaFuncAttributeMaxDynamicSharedMemorySize, SMEM_MMA);
        cudaFuncSetAttribute(mma_big<3>, cudaFuncAttributeMaxDynamicSharedMemorySize, SMEM_MMA);
        cudaFuncSetAttribute(step_fused, cudaFuncAttributeMaxDynamicSharedMemorySize, SMEM_MMA);
        attr_done = true;
    }

    mean_split<<<(Bb * Ec) / 256, 256>>>(image);

    auto nblk = [](int total) { return (total + 255) / 256; };
    split_kernel<<<nblk(1024*1024), 256>>>(W_h,  1024, 0,    1024, 1024, 1024*1024, 0);
    split_kernel<<<nblk(1024*1024), 256>>>(W_m,  1024, 0,    1024, 1024, 1024*1024, 1);
    split_kernel<<<nblk(4096*1024), 256>>>(W_ih, 1152, 0,    1024, 4096, 4096*1024, 2);
    split_kernel<<<nblk(4096*128),  256>>>(W_ih, 1152, 1024, 128,  4096, 4096*128,  3);
    split_kernel<<<nblk(4096*1024), 256>>>(W_hh, 1024, 0,    1024, 4096, 4096*1024, 4);
    split_kernel<<<nblk(FCPAD*1024),256>>>(W_fc, 1024, 0,    1024, FCOUT, FCPAD*1024, 5);
    split_kernel<<<nblk(Bb*Tc*Lc),  256>>>(label, Lc,  0,    Lc,   Bb*Tc, Bb*Tc*Lc,  6);

    mma_big<1><<<dim3(64, 4), 128, SMEM_MMA>>>(b_ih, b_hh);
    mma_big<2><<<dim3(16, 4), 128, SMEM_MMA>>>(b_h, nullptr);
    mma_big<3><<<dim3(16, 4), 128, SMEM_MMA>>>(b_m, nullptr);

    // step t: gates_t (x<64) + fc_{t-1} (x in 64..82); t=Tc runs fc_{Tc-1} only
    for (int t = 0; t <= Tc; ++t) {
        step_fused<<<dim3(83, 4), 128, SMEM_MMA>>>(b_fc, length, out, t);
    }
}